// round 1
// baseline (speedup 1.0000x reference)
#include <cuda_runtime.h>
#include <math.h>

// Problem dims
#define B_DIM 256
#define K_DIM 4096   // = I = H = O

// GEMM tile config
#define BM 128
#define BN 64
#define BK 16
#define PAD 20       // BK + 4: conflict-free LDS, keeps 16B alignment
#define NSTAGE 3
#define NTHREADS 256

// Scratch (allocation-free rule: __device__ globals)
__device__ float g_hn[B_DIM * K_DIM];
__device__ float g_logits[B_DIM * K_DIM];

// ---------------- low-level helpers ----------------

__device__ __forceinline__ unsigned f2tf(float f) {
    unsigned r;
    asm("cvt.rna.tf32.f32 %0, %1;" : "=r"(r) : "f"(f));
    return r;
}

__device__ __forceinline__ void mma8(float c[4], const unsigned a[4], const unsigned b[2]) {
    asm volatile(
        "mma.sync.aligned.m16n8k8.row.col.f32.tf32.tf32.f32 "
        "{%0,%1,%2,%3}, {%4,%5,%6,%7}, {%8,%9}, {%0,%1,%2,%3};\n"
        : "+f"(c[0]), "+f"(c[1]), "+f"(c[2]), "+f"(c[3])
        : "r"(a[0]), "r"(a[1]), "r"(a[2]), "r"(a[3]),
          "r"(b[0]), "r"(b[1]));
}

__device__ __forceinline__ void cp_async16(void* smem_dst, const void* gsrc) {
    unsigned s = (unsigned)__cvta_generic_to_shared(smem_dst);
    asm volatile("cp.async.cg.shared.global [%0], [%1], 16;\n" :: "r"(s), "l"(gsrc));
}
__device__ __forceinline__ void cp_commit() {
    asm volatile("cp.async.commit_group;\n");
}
template <int N>
__device__ __forceinline__ void cp_wait() {
    asm volatile("cp.async.wait_group %0;\n" :: "n"(N));
}

// ---------------- GEMM core ----------------
// C[M,N] (+)= A[M,K_DIM] * Bw[N,K_DIM]^T   (both row-major, K contiguous)
// CTA tile 128x64, warp tile 32x32 (warps 4x2), mma m16n8k8 tf32.

__device__ __forceinline__ void issue_stage(const float* __restrict__ A,
                                            const float* __restrict__ Bw,
                                            int kt, float* As, float* Bs, int stage) {
    int t = threadIdx.x;
    int row = t >> 2;        // 0..63
    int vec = t & 3;         // 0..3 (x4 floats)
    size_t gofs = (size_t)kt * BK + vec * 4;
    {
        float* dst = As + stage * (BM * PAD) + row * PAD + vec * 4;
        const float* src = A + ((size_t)blockIdx.y * BM + row) * K_DIM + gofs;
        cp_async16(dst, src);
        cp_async16(dst + 64 * PAD, src + (size_t)64 * K_DIM);
    }
    {
        float* dst = Bs + stage * (BN * PAD) + row * PAD + vec * 4;
        const float* src = Bw + ((size_t)blockIdx.x * BN + row) * K_DIM + gofs;
        cp_async16(dst, src);
    }
}

__device__ __forceinline__ void compute_stage(const float* __restrict__ As,
                                              const float* __restrict__ Bs,
                                              float acc[2][4][4], int wm, int wn, int lane) {
    int g = lane >> 2;   // 0..7
    int t = lane & 3;    // 0..3
#pragma unroll
    for (int ks = 0; ks < 2; ks++) {
        int col = ks * 8 + t;
        unsigned af[2][4];
#pragma unroll
        for (int mi = 0; mi < 2; mi++) {
            int r = wm + mi * 16 + g;
            af[mi][0] = f2tf(As[r * PAD + col]);
            af[mi][1] = f2tf(As[(r + 8) * PAD + col]);
            af[mi][2] = f2tf(As[r * PAD + col + 4]);
            af[mi][3] = f2tf(As[(r + 8) * PAD + col + 4]);
        }
        unsigned bf[4][2];
#pragma unroll
        for (int ni = 0; ni < 4; ni++) {
            int r = wn + ni * 8 + g;
            bf[ni][0] = f2tf(Bs[r * PAD + col]);
            bf[ni][1] = f2tf(Bs[r * PAD + col + 4]);
        }
#pragma unroll
        for (int mi = 0; mi < 2; mi++)
#pragma unroll
            for (int ni = 0; ni < 4; ni++)
                mma8(acc[mi][ni], af[mi], bf[ni]);
    }
}

__device__ __forceinline__ void gemm_pipeline(const float* __restrict__ A,
                                              const float* __restrict__ Bw,
                                              float* As, float* Bs,
                                              float acc[2][4][4]) {
    const int KT = K_DIM / BK;  // 256
    int lane = threadIdx.x & 31;
    int warp = threadIdx.x >> 5;
    int wm = (warp >> 1) * 32;
    int wn = (warp & 1) * 32;

    __syncthreads();  // buffers free (vs previous phase consumers)

    issue_stage(A, Bw, 0, As, Bs, 0); cp_commit();
    issue_stage(A, Bw, 1, As, Bs, 1); cp_commit();

    int s_cmp = 0, s_load = 2;
    for (int kt = 0; kt < KT; kt++) {
        cp_wait<1>();
        __syncthreads();
        if (kt + 2 < KT) issue_stage(A, Bw, kt + 2, As, Bs, s_load);
        cp_commit();
        compute_stage(As + s_cmp * (BM * PAD), Bs + s_cmp * (BN * PAD), acc, wm, wn, lane);
        s_cmp = (s_cmp == NSTAGE - 1) ? 0 : s_cmp + 1;
        s_load = (s_load == NSTAGE - 1) ? 0 : s_load + 1;
    }
    __syncthreads();
}

// ---------------- kernels ----------------

__global__ void __launch_bounds__(NTHREADS, 1)
gemm1_kernel(const float* __restrict__ x, const float* __restrict__ h,
             const float* __restrict__ wih, const float* __restrict__ whh,
             const float* __restrict__ bih, const float* __restrict__ bhh,
             float* __restrict__ out_hn) {
    __shared__ float As[NSTAGE * BM * PAD];
    __shared__ float Bs[NSTAGE * BN * PAD];

    float acc[2][4][4];
#pragma unroll
    for (int i = 0; i < 2; i++)
#pragma unroll
        for (int j = 0; j < 4; j++)
#pragma unroll
            for (int k = 0; k < 4; k++) acc[i][j][k] = 0.0f;

    gemm_pipeline(x, wih, As, Bs, acc);
    gemm_pipeline(h, whh, As, Bs, acc);

    int lane = threadIdx.x & 31;
    int warp = threadIdx.x >> 5;
    int wm = blockIdx.y * BM + (warp >> 1) * 32;
    int wn = blockIdx.x * BN + (warp & 1) * 32;
    int g = lane >> 2, t = lane & 3;

#pragma unroll
    for (int mi = 0; mi < 2; mi++) {
#pragma unroll
        for (int ni = 0; ni < 4; ni++) {
            int r = wm + mi * 16 + g;
            int c = wn + ni * 8 + t * 2;
            float bias0 = bih[c] + bhh[c];
            float bias1 = bih[c + 1] + bhh[c + 1];
            float v0 = tanhf(acc[mi][ni][0] + bias0);
            float v1 = tanhf(acc[mi][ni][1] + bias1);
            float v2 = tanhf(acc[mi][ni][2] + bias0);
            float v3 = tanhf(acc[mi][ni][3] + bias1);
            size_t o0 = (size_t)r * K_DIM + c;
            size_t o2 = (size_t)(r + 8) * K_DIM + c;
            g_hn[o0] = v0;     g_hn[o0 + 1] = v1;
            g_hn[o2] = v2;     g_hn[o2 + 1] = v3;
            out_hn[o0] = v0;   out_hn[o0 + 1] = v1;
            out_hn[o2] = v2;   out_hn[o2 + 1] = v3;
        }
    }
}

__global__ void __launch_bounds__(NTHREADS, 1)
gemm2_kernel(const float* __restrict__ wlin, const float* __restrict__ blin) {
    __shared__ float As[NSTAGE * BM * PAD];
    __shared__ float Bs[NSTAGE * BN * PAD];

    float acc[2][4][4];
#pragma unroll
    for (int i = 0; i < 2; i++)
#pragma unroll
        for (int j = 0; j < 4; j++)
#pragma unroll
            for (int k = 0; k < 4; k++) acc[i][j][k] = 0.0f;

    gemm_pipeline(g_hn, wlin, As, Bs, acc);

    int lane = threadIdx.x & 31;
    int warp = threadIdx.x >> 5;
    int wm = blockIdx.y * BM + (warp >> 1) * 32;
    int wn = blockIdx.x * BN + (warp & 1) * 32;
    int g = lane >> 2, t = lane & 3;

#pragma unroll
    for (int mi = 0; mi < 2; mi++) {
#pragma unroll
        for (int ni = 0; ni < 4; ni++) {
            int r = wm + mi * 16 + g;
            int c = wn + ni * 8 + t * 2;
            float b0 = blin[c], b1 = blin[c + 1];
            size_t o0 = (size_t)r * K_DIM + c;
            size_t o2 = (size_t)(r + 8) * K_DIM + c;
            g_logits[o0] = acc[mi][ni][0] + b0;
            g_logits[o0 + 1] = acc[mi][ni][1] + b1;
            g_logits[o2] = acc[mi][ni][2] + b0;
            g_logits[o2 + 1] = acc[mi][ni][3] + b1;
        }
    }
}

__global__ void __launch_bounds__(256)
softmax_kernel(float* __restrict__ probs) {
    int row = blockIdx.x;
    int tid = threadIdx.x;
    const float* lr = g_logits + (size_t)row * K_DIM;
    __shared__ float red[256];

    float m = -1e30f;
    for (int i = tid; i < K_DIM; i += 256) m = fmaxf(m, lr[i]);
    red[tid] = m;
    __syncthreads();
    for (int s = 128; s > 0; s >>= 1) {
        if (tid < s) red[tid] = fmaxf(red[tid], red[tid + s]);
        __syncthreads();
    }
    m = red[0];
    __syncthreads();

    float sum = 0.0f;
    for (int i = tid; i < K_DIM; i += 256) sum += expf(lr[i] - m);
    red[tid] = sum;
    __syncthreads();
    for (int s = 128; s > 0; s >>= 1) {
        if (tid < s) red[tid] += red[tid + s];
        __syncthreads();
    }
    float inv = 1.0f / red[0];

    float* pr = probs + (size_t)row * K_DIM;
    for (int i = tid; i < K_DIM; i += 256) pr[i] = expf(lr[i] - m) * inv;
}

// ---------------- launch ----------------

extern "C" void kernel_launch(void* const* d_in, const int* in_sizes, int n_in,
                              void* d_out, int out_size) {
    const float* x    = (const float*)d_in[0];
    const float* h0   = (const float*)d_in[1];   // [1,B,H] contiguous
    const float* wih  = (const float*)d_in[2];
    const float* bih  = (const float*)d_in[3];
    const float* whh  = (const float*)d_in[4];
    const float* bhh  = (const float*)d_in[5];
    const float* wlin = (const float*)d_in[6];
    const float* blin = (const float*)d_in[7];

    float* out = (float*)d_out;
    float* probs_out = out;                              // [1,B,O]
    float* hn_out    = out + (size_t)B_DIM * K_DIM;      // [1,B,H]

    dim3 grid(K_DIM / BN, B_DIM / BM);  // (64, 2)
    gemm1_kernel<<<grid, NTHREADS>>>(x, h0, wih, whh, bih, bhh, hn_out);
    gemm2_kernel<<<grid, NTHREADS>>>(wlin, blin);
    softmax_kernel<<<B_DIM, 256>>>(probs_out);
}

// round 3
// speedup vs baseline: 1.1323x; 1.1323x over previous
#include <cuda_runtime.h>
#include <stdint.h>
#include <math.h>

#define B_DIM 256
#define K_DIM 4096

#define BM 128
#define BN 64
#define BK 32
#define ROWF 36                    // floats per SMEM row (BK + 4 pad; 16B-aligned, conflict-free)
#define NST 3
#define STAGE_FLOATS ((BM + BN) * ROWF)   // 6912 floats = 27648 B / stage
#define NTHREADS 256
#define SPLITK1 4                  // GEMM1: fused K=8192 -> 2048 per CTA
#define SPLITK2 4                  // GEMM2: K=4096 -> 1024 per CTA

// scratch (allocation-free rule: __device__ globals)
__device__ float g_part[SPLITK1 * B_DIM * K_DIM];   // 16 MB split-K partials
__device__ float g_hn[B_DIM * K_DIM];               // tf32-pre-rounded hidden state

// ---------------- helpers ----------------

__device__ __forceinline__ unsigned f2tf(float f) {
    unsigned r;
    asm("cvt.rna.tf32.f32 %0, %1;" : "=r"(r) : "f"(f));
    return r;
}

__device__ __forceinline__ void mma8(float c[4], const unsigned a[4], const unsigned b[2]) {
    asm volatile(
        "mma.sync.aligned.m16n8k8.row.col.f32.tf32.tf32.f32 "
        "{%0,%1,%2,%3}, {%4,%5,%6,%7}, {%8,%9}, {%0,%1,%2,%3};\n"
        : "+f"(c[0]), "+f"(c[1]), "+f"(c[2]), "+f"(c[3])
        : "r"(a[0]), "r"(a[1]), "r"(a[2]), "r"(a[3]),
          "r"(b[0]), "r"(b[1]));
}

__device__ __forceinline__ void cp_async16(void* smem_dst, const void* gsrc) {
    unsigned s = (unsigned)__cvta_generic_to_shared(smem_dst);
    asm volatile("cp.async.cg.shared.global [%0], [%1], 16;\n" :: "r"(s), "l"(gsrc));
}
__device__ __forceinline__ void cp_commit() {
    asm volatile("cp.async.commit_group;\n");
}
template <int N>
__device__ __forceinline__ void cp_wait() {
    asm volatile("cp.async.wait_group %0;\n" :: "n"(N));
}

// RNA-convert 4 fp32 in SMEM to tf32 bit patterns, in place
__device__ __forceinline__ void cvt_vec_s(float* p) {
    unsigned s = (unsigned)__cvta_generic_to_shared(p);
    float a, b, c, d;
    asm volatile("ld.shared.v4.f32 {%0,%1,%2,%3}, [%4];"
                 : "=f"(a), "=f"(b), "=f"(c), "=f"(d) : "r"(s));
    uint32_t x = f2tf(a), y = f2tf(b), z = f2tf(c), w = f2tf(d);
    asm volatile("st.shared.v4.b32 [%0], {%1,%2,%3,%4};"
                 :: "r"(s), "r"(x), "r"(y), "r"(z), "r"(w) : "memory");
}

// ---------------- GEMM (split-K partial) ----------------
// Writes partial C tile [BM x BN] over a K range into g_part[z].
// A rows K-contiguous, B (weights) rows K-contiguous (C = A * B^T).

struct TileArgs {
    const float* A;
    const float* Bw;
    size_t koff;   // float offset into the K dimension
};

template <int GEMM>
__global__ void __launch_bounds__(NTHREADS, 2)
gemm_splitk_kernel(const float* __restrict__ x, const float* __restrict__ h0,
                   const float* __restrict__ w0, const float* __restrict__ w1,
                   int KT) {
    extern __shared__ float sm[];   // NST stages: [A BM*ROWF][B BN*ROWF]

    const int t = threadIdx.x;
    const int z = blockIdx.z;

    // resolve split-K sources
    const float* A;
    const float* Bw;
    size_t koff;
    if (GEMM == 1) {
        if (z < 2) { A = x;  Bw = w0; koff = (size_t)z * (2 * K_DIM / SPLITK1); }
        else       { A = h0; Bw = w1; koff = (size_t)(z - 2) * (2 * K_DIM / SPLITK1); }
    } else {
        A = g_hn; Bw = w0; koff = (size_t)z * (K_DIM / SPLITK2);
    }

    // load geometry: A = 4 vec16/thread, B = 2 vec16/thread
    unsigned offA[4], offB[2];
    const float* srcA[4];
    const float* srcB[2];
#pragma unroll
    for (int i = 0; i < 4; i++) {
        int v = t + i * NTHREADS;         // 0..1023
        int row = v >> 3, vc = v & 7;
        offA[i] = row * ROWF + vc * 4;
        srcA[i] = A + ((size_t)(blockIdx.y * BM + row)) * K_DIM + koff + vc * 4;
    }
#pragma unroll
    for (int i = 0; i < 2; i++) {
        int v = t + i * NTHREADS;         // 0..511
        int row = v >> 3, vc = v & 7;
        offB[i] = BM * ROWF + row * ROWF + vc * 4;
        srcB[i] = Bw + ((size_t)(blockIdx.x * BN + row)) * K_DIM + koff + vc * 4;
    }

    float acc[2][4][4];
#pragma unroll
    for (int i = 0; i < 2; i++)
#pragma unroll
        for (int j = 0; j < 4; j++)
#pragma unroll
            for (int k = 0; k < 4; k++) acc[i][j][k] = 0.0f;

    const int lane = t & 31, warp = t >> 5;
    const int wm = (warp >> 1) * 32, wn = (warp & 1) * 32;
    const int g = lane >> 2, tc = lane & 3;

    // preload stages 0,1
#pragma unroll
    for (int s = 0; s < 2; s++) {
        float* sb = sm + s * STAGE_FLOATS;
        size_t ko = (size_t)s * BK;
#pragma unroll
        for (int i = 0; i < 4; i++) cp_async16(sb + offA[i], srcA[i] + ko);
#pragma unroll
        for (int i = 0; i < 2; i++) cp_async16(sb + offB[i], srcB[i] + ko);
        cp_commit();
    }

    for (int kt = 0; kt < KT; kt++) {
        const int sc = kt % NST;
        float* sb = sm + sc * STAGE_FLOATS;

        cp_wait<1>();
        // convert own loaded vectors fp32 -> tf32 bits, in place
#pragma unroll
        for (int i = 0; i < 4; i++) cvt_vec_s(sb + offA[i]);
#pragma unroll
        for (int i = 0; i < 2; i++) cvt_vec_s(sb + offB[i]);
        __syncthreads();   // cvt visible to all; prev compute done -> buf (kt+2)%NST free

        if (kt + 2 < KT) {
            float* lb = sm + ((kt + 2) % NST) * STAGE_FLOATS;
            size_t ko = (size_t)(kt + 2) * BK;
#pragma unroll
            for (int i = 0; i < 4; i++) cp_async16(lb + offA[i], srcA[i] + ko);
#pragma unroll
            for (int i = 0; i < 2; i++) cp_async16(lb + offB[i], srcB[i] + ko);
        }
        cp_commit();

        // compute on tf32 bit patterns
        const unsigned* Au = (const unsigned*)sb;
        const unsigned* Bu = (const unsigned*)(sb + BM * ROWF);
#pragma unroll
        for (int ks = 0; ks < 4; ks++) {
            int col = ks * 8 + tc;
            unsigned af[2][4];
#pragma unroll
            for (int mi = 0; mi < 2; mi++) {
                int r = wm + mi * 16 + g;
                af[mi][0] = Au[r * ROWF + col];
                af[mi][1] = Au[(r + 8) * ROWF + col];
                af[mi][2] = Au[r * ROWF + col + 4];
                af[mi][3] = Au[(r + 8) * ROWF + col + 4];
            }
            unsigned bf[4][2];
#pragma unroll
            for (int ni = 0; ni < 4; ni++) {
                int r = wn + ni * 8 + g;
                bf[ni][0] = Bu[r * ROWF + col];
                bf[ni][1] = Bu[r * ROWF + col + 4];
            }
#pragma unroll
            for (int mi = 0; mi < 2; mi++)
#pragma unroll
                for (int ni = 0; ni < 4; ni++)
                    mma8(acc[mi][ni], af[mi], bf[ni]);
        }
    }

    // write partial tile
    float* part = g_part + (size_t)z * (B_DIM * K_DIM);
#pragma unroll
    for (int mi = 0; mi < 2; mi++) {
#pragma unroll
        for (int ni = 0; ni < 4; ni++) {
            int gr = blockIdx.y * BM + wm + mi * 16 + g;
            int gc = blockIdx.x * BN + wn + ni * 8 + tc * 2;
            size_t o0 = (size_t)gr * K_DIM + gc;
            size_t o2 = (size_t)(gr + 8) * K_DIM + gc;
            *(float2*)(part + o0) = make_float2(acc[mi][ni][0], acc[mi][ni][1]);
            *(float2*)(part + o2) = make_float2(acc[mi][ni][2], acc[mi][ni][3]);
        }
    }
}

// ---------------- reduce1: hn = tanh(sum partials + bih + bhh) ----------------

__global__ void __launch_bounds__(256)
reduce1_kernel(const float* __restrict__ bih, const float* __restrict__ bhh,
               float* __restrict__ hn_out) {
    size_t v4 = (size_t)blockIdx.x * 256 + threadIdx.x;   // float4 index
    size_t e = v4 * 4;
    int col = (int)(e & (K_DIM - 1));
    float4 p0 = *(const float4*)(g_part + e);
    float4 p1 = *(const float4*)(g_part + (size_t)1 * B_DIM * K_DIM + e);
    float4 p2 = *(const float4*)(g_part + (size_t)2 * B_DIM * K_DIM + e);
    float4 p3 = *(const float4*)(g_part + (size_t)3 * B_DIM * K_DIM + e);
    float4 ba = *(const float4*)(bih + col);
    float4 bb = *(const float4*)(bhh + col);
    float t0 = tanhf(p0.x + p1.x + p2.x + p3.x + ba.x + bb.x);
    float t1 = tanhf(p0.y + p1.y + p2.y + p3.y + ba.y + bb.y);
    float t2 = tanhf(p0.z + p1.z + p2.z + p3.z + ba.z + bb.z);
    float t3 = tanhf(p0.w + p1.w + p2.w + p3.w + ba.w + bb.w);
    *(float4*)(hn_out + e) = make_float4(t0, t1, t2, t3);
    // pre-rounded copy for GEMM2 (cvt there becomes identity; bias already exact)
    *(float4*)(g_hn + e) = make_float4(__uint_as_float(f2tf(t0)), __uint_as_float(f2tf(t1)),
                                       __uint_as_float(f2tf(t2)), __uint_as_float(f2tf(t3)));
}

// ---------------- softmax (fuses GEMM2 split-K reduce + bias) ----------------

__global__ void __launch_bounds__(256)
softmax_kernel(const float* __restrict__ blin, float* __restrict__ probs) {
    __shared__ float sl[K_DIM];        // 16 KB logits row
    __shared__ float red[256];
    const int row = blockIdx.x, tid = threadIdx.x;
    const size_t rb = (size_t)row * K_DIM;

    float m = -1e30f;
    for (int i = tid * 4; i < K_DIM; i += 256 * 4) {
        float4 p0 = *(const float4*)(g_part + rb + i);
        float4 p1 = *(const float4*)(g_part + (size_t)1 * B_DIM * K_DIM + rb + i);
        float4 p2 = *(const float4*)(g_part + (size_t)2 * B_DIM * K_DIM + rb + i);
        float4 p3 = *(const float4*)(g_part + (size_t)3 * B_DIM * K_DIM + rb + i);
        float4 b  = *(const float4*)(blin + i);
        float v0 = p0.x + p1.x + p2.x + p3.x + b.x;
        float v1 = p0.y + p1.y + p2.y + p3.y + b.y;
        float v2 = p0.z + p1.z + p2.z + p3.z + b.z;
        float v3 = p0.w + p1.w + p2.w + p3.w + b.w;
        *(float4*)(sl + i) = make_float4(v0, v1, v2, v3);
        m = fmaxf(m, fmaxf(fmaxf(v0, v1), fmaxf(v2, v3)));
    }
    red[tid] = m;
    __syncthreads();
    for (int s = 128; s > 0; s >>= 1) {
        if (tid < s) red[tid] = fmaxf(red[tid], red[tid + s]);
        __syncthreads();
    }
    m = red[0];
    __syncthreads();

    float sum = 0.0f;
    for (int i = tid; i < K_DIM; i += 256) sum += expf(sl[i] - m);
    red[tid] = sum;
    __syncthreads();
    for (int s = 128; s > 0; s >>= 1) {
        if (tid < s) red[tid] += red[tid + s];
        __syncthreads();
    }
    float inv = 1.0f / red[0];

    for (int i = tid; i < K_DIM; i += 256)
        probs[rb + i] = expf(sl[i] - m) * inv;
}

// ---------------- launch ----------------

extern "C" void kernel_launch(void* const* d_in, const int* in_sizes, int n_in,
                              void* d_out, int out_size) {
    const float* x    = (const float*)d_in[0];
    const float* h0   = (const float*)d_in[1];
    const float* wih  = (const float*)d_in[2];
    const float* bih  = (const float*)d_in[3];
    const float* whh  = (const float*)d_in[4];
    const float* bhh  = (const float*)d_in[5];
    const float* wlin = (const float*)d_in[6];
    const float* blin = (const float*)d_in[7];

    float* out = (float*)d_out;
    float* probs_out = out;
    float* hn_out    = out + (size_t)B_DIM * K_DIM;

    const int dyn = NST * STAGE_FLOATS * sizeof(float);   // 82944 B
    cudaFuncSetAttribute(gemm_splitk_kernel<1>, cudaFuncAttributeMaxDynamicSharedMemorySize, dyn);
    cudaFuncSetAttribute(gemm_splitk_kernel<2>, cudaFuncAttributeMaxDynamicSharedMemorySize, dyn);

    // GEMM1: partials of x@wih^T + h0@whh^T, fused K=8192, split 4
    dim3 grid1(K_DIM / BN, B_DIM / BM, SPLITK1);   // (64, 2, 4)
    gemm_splitk_kernel<1><<<grid1, NTHREADS, dyn>>>(x, h0, wih, whh,
                                                    (2 * K_DIM / SPLITK1) / BK);  // KT=64
    // reduce + biases + tanh
    reduce1_kernel<<<(B_DIM * K_DIM) / (256 * 4), 256>>>(bih, bhh, hn_out);

    // GEMM2: partials of hn@wlin^T, K=4096, split 4
    dim3 grid2(K_DIM / BN, B_DIM / BM, SPLITK2);
    gemm_splitk_kernel<2><<<grid2, NTHREADS, dyn>>>(nullptr, nullptr, wlin, nullptr,
                                                    (K_DIM / SPLITK2) / BK);      // KT=32
    // softmax fuses split-K reduce + blin
    softmax_kernel<<<B_DIM, 256>>>(blin, probs_out);
}

// round 4
// speedup vs baseline: 1.4861x; 1.3124x over previous
#include <cuda_runtime.h>
#include <stdint.h>
#include <math.h>

#define B_DIM 256
#define K_DIM 4096

#define BM 256              // full batch: weights stream once
#define BN 64
#define BK 32
#define ROWF 36             // BK + 4 pad (conflict-free)
#define NST 4
#define STAGE_FLOATS ((BM + BN) * ROWF)            // 11520 floats = 46080 B
#define NTHREADS 256
#define SPLITK1 4           // fused K=8192 -> 2048 per CTA
#define SPLITK2 4           // K=4096 -> 1024 per CTA

// scratch (allocation-free rule)
__device__ float g_part[4 * B_DIM * K_DIM];   // split-K partials (16 MB)
__device__ float g_xh[2 * B_DIM * K_DIM];     // tf32-pre-rounded [x ; h0]
__device__ float g_hn[B_DIM * K_DIM];         // tf32-pre-rounded hidden state

// ---------------- helpers ----------------

__device__ __forceinline__ unsigned f2tf(float f) {
    unsigned r;
    asm("cvt.rna.tf32.f32 %0, %1;" : "=r"(r) : "f"(f));
    return r;
}

__device__ __forceinline__ void mma8(float c[4], const unsigned a[4], const unsigned b[2]) {
    asm volatile(
        "mma.sync.aligned.m16n8k8.row.col.f32.tf32.tf32.f32 "
        "{%0,%1,%2,%3}, {%4,%5,%6,%7}, {%8,%9}, {%0,%1,%2,%3};\n"
        : "+f"(c[0]), "+f"(c[1]), "+f"(c[2]), "+f"(c[3])
        : "r"(a[0]), "r"(a[1]), "r"(a[2]), "r"(a[3]),
          "r"(b[0]), "r"(b[1]));
}

__device__ __forceinline__ void cp_async16(void* smem_dst, const void* gsrc) {
    unsigned s = (unsigned)__cvta_generic_to_shared(smem_dst);
    asm volatile("cp.async.cg.shared.global [%0], [%1], 16;\n" :: "r"(s), "l"(gsrc));
}
__device__ __forceinline__ void cp_commit() {
    asm volatile("cp.async.commit_group;\n");
}
template <int N>
__device__ __forceinline__ void cp_wait() {
    asm volatile("cp.async.wait_group %0;\n" :: "n"(N));
}

// ---------------- prep: round x,h0 to tf32 once ----------------

__global__ void __launch_bounds__(256)
prep_kernel(const float* __restrict__ x, const float* __restrict__ h0) {
    size_t v4 = (size_t)blockIdx.x * 256 + threadIdx.x;
    size_t e = v4 * 4;
    const size_t half = (size_t)B_DIM * K_DIM;
    const float* src = (e < half) ? (x + e) : (h0 + (e - half));
    float4 p = *(const float4*)src;
    *(float4*)(g_xh + e) = make_float4(
        __uint_as_float(f2tf(p.x)), __uint_as_float(f2tf(p.y)),
        __uint_as_float(f2tf(p.z)), __uint_as_float(f2tf(p.w)));
}

// ---------------- GEMM (split-K partial) ----------------
// C tile [256 x 64] over a K range -> g_part[z].
// A: pre-rounded tf32 bits (no cvt). B: raw fp32 weights, cvt in regs.

template <int GEMM>
__global__ void __launch_bounds__(NTHREADS, 1)
gemm_splitk_kernel(const float* __restrict__ w0, const float* __restrict__ w1,
                   int KT) {
    extern __shared__ float sm[];

    const int t = threadIdx.x;
    const int z = blockIdx.z;
    const int bx = blockIdx.x;

    // resolve split-K sources
    const float* A;   // pre-rounded, rows = batch, K-contiguous
    const float* Bw;  // weights, rows = out-features, K-contiguous
    size_t koff;
    if (GEMM == 1) {
        A = g_xh + (z >= 2 ? (size_t)B_DIM * K_DIM : 0);
        Bw = (z < 2) ? w0 : w1;
        koff = (size_t)(z & 1) * (K_DIM / 2);            // 2048
    } else {
        A = g_hn; Bw = w0;
        koff = (size_t)z * (K_DIM / SPLITK2);            // 1024
    }

    // load geometry: 10 vec16 per thread; rows advance by 32 per vec
    const int r0 = t >> 3;          // 0..31
    const int vc = t & 7;           // 16B vec in 128B row
    const float* srcA = A + (size_t)r0 * K_DIM + koff + vc * 4;          // rows r0+32i, i=0..7
    const float* srcB = Bw + ((size_t)(bx * BN + r0)) * K_DIM + koff + vc * 4;  // rows r0+32(i-8)
    float* dst0 = sm + r0 * ROWF + vc * 4;

    float acc[4][4][4];
#pragma unroll
    for (int i = 0; i < 4; i++)
#pragma unroll
        for (int j = 0; j < 4; j++)
#pragma unroll
            for (int k = 0; k < 4; k++) acc[i][j][k] = 0.0f;

    const int lane = t & 31, warp = t >> 5;
    const int wm = (warp >> 1) * 64;    // 4 warps along M
    const int wn = (warp & 1) * 32;     // 2 warps along N
    const int g = lane >> 2, tc = lane & 3;

    // prologue: stages 0..NST-2
#pragma unroll
    for (int s = 0; s < NST - 1; s++) {
        float* sb = dst0 + s * STAGE_FLOATS;
        size_t ko = (size_t)s * BK;
#pragma unroll
        for (int i = 0; i < 8; i++) cp_async16(sb + i * 32 * ROWF, srcA + ko + (size_t)i * 32 * K_DIM);
#pragma unroll
        for (int i = 0; i < 2; i++) cp_async16(sb + (256 + i * 32) * ROWF, srcB + ko + (size_t)i * 32 * K_DIM);
        cp_commit();
    }

    for (int kt = 0; kt < KT; kt++) {
        const int sc = kt % NST;
        float* sb = sm + sc * STAGE_FLOATS;

        cp_wait<NST - 2>();
        __syncthreads();

        if (kt + NST - 1 < KT) {
            float* lb = dst0 + ((kt + NST - 1) % NST) * STAGE_FLOATS;
            size_t ko = (size_t)(kt + NST - 1) * BK;
#pragma unroll
            for (int i = 0; i < 8; i++) cp_async16(lb + i * 32 * ROWF, srcA + ko + (size_t)i * 32 * K_DIM);
#pragma unroll
            for (int i = 0; i < 2; i++) cp_async16(lb + (256 + i * 32) * ROWF, srcB + ko + (size_t)i * 32 * K_DIM);
        }
        cp_commit();

        const unsigned* Au = (const unsigned*)sb;                 // rows 0..255 (tf32 bits)
        const float*    Bf = sb + 256 * ROWF;                     // rows 0..63 (raw fp32)
#pragma unroll
        for (int ks = 0; ks < 4; ks++) {
            const int col = ks * 8 + tc;
            unsigned af[4][4];
#pragma unroll
            for (int mi = 0; mi < 4; mi++) {
                int r = wm + mi * 16 + g;
                af[mi][0] = Au[r * ROWF + col];
                af[mi][1] = Au[(r + 8) * ROWF + col];
                af[mi][2] = Au[r * ROWF + col + 4];
                af[mi][3] = Au[(r + 8) * ROWF + col + 4];
            }
            unsigned bf[4][2];
#pragma unroll
            for (int ni = 0; ni < 4; ni++) {
                int r = wn + ni * 8 + g;
                bf[ni][0] = f2tf(Bf[r * ROWF + col]);
                bf[ni][1] = f2tf(Bf[r * ROWF + col + 4]);
            }
#pragma unroll
            for (int mi = 0; mi < 4; mi++)
#pragma unroll
                for (int ni = 0; ni < 4; ni++)
                    mma8(acc[mi][ni], af[mi], bf[ni]);
        }
    }

    // write partial tile
    float* part = g_part + (size_t)z * (B_DIM * K_DIM);
#pragma unroll
    for (int mi = 0; mi < 4; mi++) {
#pragma unroll
        for (int ni = 0; ni < 4; ni++) {
            int gr = wm + mi * 16 + g;
            int gc = bx * BN + wn + ni * 8 + tc * 2;
            size_t o0 = (size_t)gr * K_DIM + gc;
            size_t o2 = (size_t)(gr + 8) * K_DIM + gc;
            *(float2*)(part + o0) = make_float2(acc[mi][ni][0], acc[mi][ni][1]);
            *(float2*)(part + o2) = make_float2(acc[mi][ni][2], acc[mi][ni][3]);
        }
    }
}

// ---------------- reduce1: hn = tanh(sum partials + bih + bhh) ----------------

__global__ void __launch_bounds__(256)
reduce1_kernel(const float* __restrict__ bih, const float* __restrict__ bhh,
               float* __restrict__ hn_out) {
    size_t v4 = (size_t)blockIdx.x * 256 + threadIdx.x;
    size_t e = v4 * 4;
    int col = (int)(e & (K_DIM - 1));
    float4 p0 = *(const float4*)(g_part + e);
    float4 p1 = *(const float4*)(g_part + (size_t)1 * B_DIM * K_DIM + e);
    float4 p2 = *(const float4*)(g_part + (size_t)2 * B_DIM * K_DIM + e);
    float4 p3 = *(const float4*)(g_part + (size_t)3 * B_DIM * K_DIM + e);
    float4 ba = *(const float4*)(bih + col);
    float4 bb = *(const float4*)(bhh + col);
    float t0 = tanhf(p0.x + p1.x + p2.x + p3.x + ba.x + bb.x);
    float t1 = tanhf(p0.y + p1.y + p2.y + p3.y + ba.y + bb.y);
    float t2 = tanhf(p0.z + p1.z + p2.z + p3.z + ba.z + bb.z);
    float t3 = tanhf(p0.w + p1.w + p2.w + p3.w + ba.w + bb.w);
    *(float4*)(hn_out + e) = make_float4(t0, t1, t2, t3);
    *(float4*)(g_hn + e) = make_float4(__uint_as_float(f2tf(t0)), __uint_as_float(f2tf(t1)),
                                       __uint_as_float(f2tf(t2)), __uint_as_float(f2tf(t3)));
}

// ---------------- softmax (fuses GEMM2 split-K reduce + bias) ----------------

__global__ void __launch_bounds__(256)
softmax_kernel(const float* __restrict__ blin, float* __restrict__ probs) {
    __shared__ float sl[K_DIM];
    __shared__ float red[256];
    const int row = blockIdx.x, tid = threadIdx.x;
    const size_t rb = (size_t)row * K_DIM;

    float m = -1e30f;
    for (int i = tid * 4; i < K_DIM; i += 256 * 4) {
        float4 p0 = *(const float4*)(g_part + rb + i);
        float4 p1 = *(const float4*)(g_part + (size_t)1 * B_DIM * K_DIM + rb + i);
        float4 p2 = *(const float4*)(g_part + (size_t)2 * B_DIM * K_DIM + rb + i);
        float4 p3 = *(const float4*)(g_part + (size_t)3 * B_DIM * K_DIM + rb + i);
        float4 b  = *(const float4*)(blin + i);
        float v0 = p0.x + p1.x + p2.x + p3.x + b.x;
        float v1 = p0.y + p1.y + p2.y + p3.y + b.y;
        float v2 = p0.z + p1.z + p2.z + p3.z + b.z;
        float v3 = p0.w + p1.w + p2.w + p3.w + b.w;
        *(float4*)(sl + i) = make_float4(v0, v1, v2, v3);
        m = fmaxf(m, fmaxf(fmaxf(v0, v1), fmaxf(v2, v3)));
    }
    red[tid] = m;
    __syncthreads();
    for (int s = 128; s > 0; s >>= 1) {
        if (tid < s) red[tid] = fmaxf(red[tid], red[tid + s]);
        __syncthreads();
    }
    m = red[0];
    __syncthreads();

    float sum = 0.0f;
    for (int i = tid; i < K_DIM; i += 256) sum += expf(sl[i] - m);
    red[tid] = sum;
    __syncthreads();
    for (int s = 128; s > 0; s >>= 1) {
        if (tid < s) red[tid] += red[tid + s];
        __syncthreads();
    }
    float inv = 1.0f / red[0];

    for (int i = tid; i < K_DIM; i += 256)
        probs[rb + i] = expf(sl[i] - m) * inv;
}

// ---------------- launch ----------------

extern "C" void kernel_launch(void* const* d_in, const int* in_sizes, int n_in,
                              void* d_out, int out_size) {
    const float* x    = (const float*)d_in[0];
    const float* h0   = (const float*)d_in[1];
    const float* wih  = (const float*)d_in[2];
    const float* bih  = (const float*)d_in[3];
    const float* whh  = (const float*)d_in[4];
    const float* bhh  = (const float*)d_in[5];
    const float* wlin = (const float*)d_in[6];
    const float* blin = (const float*)d_in[7];

    float* out = (float*)d_out;
    float* probs_out = out;
    float* hn_out    = out + (size_t)B_DIM * K_DIM;

    const int dyn = NST * STAGE_FLOATS * sizeof(float);   // 184320 B
    cudaFuncSetAttribute(gemm_splitk_kernel<1>, cudaFuncAttributeMaxDynamicSharedMemorySize, dyn);
    cudaFuncSetAttribute(gemm_splitk_kernel<2>, cudaFuncAttributeMaxDynamicSharedMemorySize, dyn);

    // round x,h0 to tf32 once (2*4MB)
    prep_kernel<<<(2 * B_DIM * K_DIM) / (256 * 4), 256>>>(x, h0);

    // GEMM1: partials of x@wih^T + h0@whh^T (fused K=8192, split 4)
    dim3 grid1(K_DIM / BN, 1, SPLITK1);    // (64,1,4) = 256 CTAs
    gemm_splitk_kernel<1><<<grid1, NTHREADS, dyn>>>(wih, whh, (K_DIM / 2) / BK);  // KT=64

    reduce1_kernel<<<(B_DIM * K_DIM) / (256 * 4), 256>>>(bih, bhh, hn_out);

    // GEMM2: partials of hn@wlin^T (K=4096, split 4)
    dim3 grid2(K_DIM / BN, 1, SPLITK2);
    gemm_splitk_kernel<2><<<grid2, NTHREADS, dyn>>>(wlin, nullptr, (K_DIM / SPLITK2) / BK);  // KT=32

    softmax_kernel<<<B_DIM, 256>>>(blin, probs_out);
}

// round 6
// speedup vs baseline: 1.4991x; 1.0088x over previous
#include <cuda_runtime.h>
#include <stdint.h>
#include <math.h>

#define B_DIM 256
#define K_DIM 4096

#define BM 256              // full batch: weights stream once
#define BN 64
#define BK 32
#define ROWF 36             // BK + 4 pad (conflict-free)
#define NST 4
#define STAGE_FLOATS ((BM + BN) * ROWF)            // 11520 floats = 46080 B
#define NTHREADS 256
#define SPLITK1 4           // fused K=8192 -> 2048 per CTA
#define SPLITK2 4           // K=4096 -> 1024 per CTA

// scratch (allocation-free rule)
__device__ float g_part[4 * B_DIM * K_DIM];   // split-K partials (16 MB)
__device__ float g_xh[2 * B_DIM * K_DIM];     // tf32-pre-rounded [x ; h0]
__device__ float g_hn[B_DIM * K_DIM];         // tf32-pre-rounded hidden state

// ---------------- helpers ----------------

__device__ __forceinline__ unsigned f2tf(float f) {
    unsigned r;
    asm("cvt.rna.tf32.f32 %0, %1;" : "=r"(r) : "f"(f));
    return r;
}

__device__ __forceinline__ void mma8(float c[4], const unsigned a[4], const unsigned b[2]) {
    asm volatile(
        "mma.sync.aligned.m16n8k8.row.col.f32.tf32.tf32.f32 "
        "{%0,%1,%2,%3}, {%4,%5,%6,%7}, {%8,%9}, {%0,%1,%2,%3};\n"
        : "+f"(c[0]), "+f"(c[1]), "+f"(c[2]), "+f"(c[3])
        : "r"(a[0]), "r"(a[1]), "r"(a[2]), "r"(a[3]),
          "r"(b[0]), "r"(b[1]));
}

__device__ __forceinline__ void cp_async16(void* smem_dst, const void* gsrc) {
    unsigned s = (unsigned)__cvta_generic_to_shared(smem_dst);
    asm volatile("cp.async.cg.shared.global [%0], [%1], 16;\n" :: "r"(s), "l"(gsrc));
}
__device__ __forceinline__ void cp_commit() {
    asm volatile("cp.async.commit_group;\n");
}
template <int N>
__device__ __forceinline__ void cp_wait() {
    asm volatile("cp.async.wait_group %0;\n" :: "n"(N));
}

// ---------------- prep: round x,h0 to tf32 once ----------------

__global__ void __launch_bounds__(256)
prep_kernel(const float* __restrict__ x, const float* __restrict__ h0) {
    size_t v4 = (size_t)blockIdx.x * 256 + threadIdx.x;
    size_t e = v4 * 4;
    const size_t half = (size_t)B_DIM * K_DIM;
    const float* src = (e < half) ? (x + e) : (h0 + (e - half));
    float4 p = *(const float4*)src;
    *(float4*)(g_xh + e) = make_float4(
        __uint_as_float(f2tf(p.x)), __uint_as_float(f2tf(p.y)),
        __uint_as_float(f2tf(p.z)), __uint_as_float(f2tf(p.w)));
}

// ---------------- GEMM (split-K partial) ----------------
// C tile [256 x 64] over a K range -> g_part[z].
// A: pre-rounded tf32 bits (no cvt). B: raw fp32 weights, cvt in regs.
// Inner loop: register ping-pong over ks to overlap LDS with HMMA.

__device__ __forceinline__ void load_afrag(unsigned af[4][4], const unsigned* Au,
                                           int wm, int g, int col) {
#pragma unroll
    for (int mi = 0; mi < 4; mi++) {
        int r = wm + mi * 16 + g;
        af[mi][0] = Au[r * ROWF + col];
        af[mi][1] = Au[(r + 8) * ROWF + col];
        af[mi][2] = Au[r * ROWF + col + 4];
        af[mi][3] = Au[(r + 8) * ROWF + col + 4];
    }
}

__device__ __forceinline__ void load_bfrag(unsigned bf[4][2], const float* Bf,
                                           int wn, int g, int col) {
#pragma unroll
    for (int ni = 0; ni < 4; ni++) {
        int r = wn + ni * 8 + g;
        bf[ni][0] = f2tf(Bf[r * ROWF + col]);
        bf[ni][1] = f2tf(Bf[r * ROWF + col + 4]);
    }
}

template <int GEMM>
__global__ void __launch_bounds__(NTHREADS, 1)
gemm_splitk_kernel(const float* __restrict__ w0, const float* __restrict__ w1,
                   int KT) {
    extern __shared__ float sm[];

    const int t = threadIdx.x;
    const int z = blockIdx.z;
    const int bx = blockIdx.x;

    // resolve split-K sources
    const float* A;   // pre-rounded, rows = batch, K-contiguous
    const float* Bw;  // weights, rows = out-features, K-contiguous
    size_t koff;
    if (GEMM == 1) {
        A = g_xh + (z >= 2 ? (size_t)B_DIM * K_DIM : 0);
        Bw = (z < 2) ? w0 : w1;
        koff = (size_t)(z & 1) * (K_DIM / 2);            // 2048
    } else {
        A = g_hn; Bw = w0;
        koff = (size_t)z * (K_DIM / SPLITK2);            // 1024
    }

    // load geometry: 10 vec16 per thread; rows advance by 32 per vec
    const int r0 = t >> 3;          // 0..31
    const int vc = t & 7;           // 16B vec in 128B row
    const float* srcA = A + (size_t)r0 * K_DIM + koff + vc * 4;
    const float* srcB = Bw + ((size_t)(bx * BN + r0)) * K_DIM + koff + vc * 4;
    float* dst0 = sm + r0 * ROWF + vc * 4;

    float acc[4][4][4];
#pragma unroll
    for (int i = 0; i < 4; i++)
#pragma unroll
        for (int j = 0; j < 4; j++)
#pragma unroll
            for (int k = 0; k < 4; k++) acc[i][j][k] = 0.0f;

    const int lane = t & 31, warp = t >> 5;
    const int wm = (warp >> 1) * 64;    // 4 warps along M
    const int wn = (warp & 1) * 32;     // 2 warps along N
    const int g = lane >> 2, tc = lane & 3;

    // prologue: stages 0..NST-2
#pragma unroll
    for (int s = 0; s < NST - 1; s++) {
        float* sb = dst0 + s * STAGE_FLOATS;
        size_t ko = (size_t)s * BK;
#pragma unroll
        for (int i = 0; i < 8; i++) cp_async16(sb + i * 32 * ROWF, srcA + ko + (size_t)i * 32 * K_DIM);
#pragma unroll
        for (int i = 0; i < 2; i++) cp_async16(sb + (256 + i * 32) * ROWF, srcB + ko + (size_t)i * 32 * K_DIM);
        cp_commit();
    }

    unsigned af[2][4][4];
    unsigned bf[2][4][2];

#pragma unroll 1
    for (int kt = 0; kt < KT; kt++) {
        const int sc = kt % NST;
        const unsigned* Au = (const unsigned*)(sm + sc * STAGE_FLOATS);
        const float*    Bf = (const float*)(Au + 256 * ROWF);

        cp_wait<NST - 2>();
        __syncthreads();   // makes ALL threads' cp.async deposits visible

        // prefetch ks=0 fragments (after barrier: cross-thread data now visible)
        load_afrag(af[0], Au, wm, g, tc);
        load_bfrag(bf[0], Bf, wn, g, tc);

        if (kt + NST - 1 < KT) {
            float* lb = dst0 + ((kt + NST - 1) % NST) * STAGE_FLOATS;
            size_t ko = (size_t)(kt + NST - 1) * BK;
#pragma unroll
            for (int i = 0; i < 8; i++) cp_async16(lb + i * 32 * ROWF, srcA + ko + (size_t)i * 32 * K_DIM);
#pragma unroll
            for (int i = 0; i < 2; i++) cp_async16(lb + (256 + i * 32) * ROWF, srcB + ko + (size_t)i * 32 * K_DIM);
        }
        cp_commit();

        // ks pipeline: load ks+1 while issuing MMAs of ks
#pragma unroll
        for (int ks = 0; ks < 4; ks++) {
            const int cur = ks & 1, nxt = cur ^ 1;
            if (ks < 3) {
                const int col = (ks + 1) * 8 + tc;
                load_afrag(af[nxt], Au, wm, g, col);
                load_bfrag(bf[nxt], Bf, wn, g, col);
            }
#pragma unroll
            for (int mi = 0; mi < 4; mi++)
#pragma unroll
                for (int ni = 0; ni < 4; ni++)
                    mma8(acc[mi][ni], af[cur][mi], bf[cur][ni]);
        }
    }

    // write partial tile
    float* part = g_part + (size_t)z * (B_DIM * K_DIM);
#pragma unroll
    for (int mi = 0; mi < 4; mi++) {
#pragma unroll
        for (int ni = 0; ni < 4; ni++) {
            int gr = wm + mi * 16 + g;
            int gc = bx * BN + wn + ni * 8 + tc * 2;
            size_t o0 = (size_t)gr * K_DIM + gc;
            size_t o2 = (size_t)(gr + 8) * K_DIM + gc;
            *(float2*)(part + o0) = make_float2(acc[mi][ni][0], acc[mi][ni][1]);
            *(float2*)(part + o2) = make_float2(acc[mi][ni][2], acc[mi][ni][3]);
        }
    }
}

// ---------------- reduce1: hn = tanh(sum partials + bih + bhh) ----------------

__global__ void __launch_bounds__(256)
reduce1_kernel(const float* __restrict__ bih, const float* __restrict__ bhh,
               float* __restrict__ hn_out) {
    size_t v4 = (size_t)blockIdx.x * 256 + threadIdx.x;
    size_t e = v4 * 4;
    int col = (int)(e & (K_DIM - 1));
    float4 p0 = *(const float4*)(g_part + e);
    float4 p1 = *(const float4*)(g_part + (size_t)1 * B_DIM * K_DIM + e);
    float4 p2 = *(const float4*)(g_part + (size_t)2 * B_DIM * K_DIM + e);
    float4 p3 = *(const float4*)(g_part + (size_t)3 * B_DIM * K_DIM + e);
    float4 ba = *(const float4*)(bih + col);
    float4 bb = *(const float4*)(bhh + col);
    float t0 = tanhf(p0.x + p1.x + p2.x + p3.x + ba.x + bb.x);
    float t1 = tanhf(p0.y + p1.y + p2.y + p3.y + ba.y + bb.y);
    float t2 = tanhf(p0.z + p1.z + p2.z + p3.z + ba.z + bb.z);
    float t3 = tanhf(p0.w + p1.w + p2.w + p3.w + ba.w + bb.w);
    *(float4*)(hn_out + e) = make_float4(t0, t1, t2, t3);
    *(float4*)(g_hn + e) = make_float4(__uint_as_float(f2tf(t0)), __uint_as_float(f2tf(t1)),
                                       __uint_as_float(f2tf(t2)), __uint_as_float(f2tf(t3)));
}

// ---------------- softmax (fuses GEMM2 split-K reduce + bias) ----------------

__global__ void __launch_bounds__(256)
softmax_kernel(const float* __restrict__ blin, float* __restrict__ probs) {
    __shared__ float sl[K_DIM];
    __shared__ float red[256];
    const int row = blockIdx.x, tid = threadIdx.x;
    const size_t rb = (size_t)row * K_DIM;

    float m = -1e30f;
    for (int i = tid * 4; i < K_DIM; i += 256 * 4) {
        float4 p0 = *(const float4*)(g_part + rb + i);
        float4 p1 = *(const float4*)(g_part + (size_t)1 * B_DIM * K_DIM + rb + i);
        float4 p2 = *(const float4*)(g_part + (size_t)2 * B_DIM * K_DIM + rb + i);
        float4 p3 = *(const float4*)(g_part + (size_t)3 * B_DIM * K_DIM + rb + i);
        float4 b  = *(const float4*)(blin + i);
        float v0 = p0.x + p1.x + p2.x + p3.x + b.x;
        float v1 = p0.y + p1.y + p2.y + p3.y + b.y;
        float v2 = p0.z + p1.z + p2.z + p3.z + b.z;
        float v3 = p0.w + p1.w + p2.w + p3.w + b.w;
        *(float4*)(sl + i) = make_float4(v0, v1, v2, v3);
        m = fmaxf(m, fmaxf(fmaxf(v0, v1), fmaxf(v2, v3)));
    }
    red[tid] = m;
    __syncthreads();
    for (int s = 128; s > 0; s >>= 1) {
        if (tid < s) red[tid] = fmaxf(red[tid], red[tid + s]);
        __syncthreads();
    }
    m = red[0];
    __syncthreads();

    float sum = 0.0f;
    for (int i = tid; i < K_DIM; i += 256) sum += expf(sl[i] - m);
    red[tid] = sum;
    __syncthreads();
    for (int s = 128; s > 0; s >>= 1) {
        if (tid < s) red[tid] += red[tid + s];
        __syncthreads();
    }
    float inv = 1.0f / red[0];

    for (int i = tid; i < K_DIM; i += 256)
        probs[rb + i] = expf(sl[i] - m) * inv;
}

// ---------------- launch ----------------

extern "C" void kernel_launch(void* const* d_in, const int* in_sizes, int n_in,
                              void* d_out, int out_size) {
    const float* x    = (const float*)d_in[0];
    const float* h0   = (const float*)d_in[1];
    const float* wih  = (const float*)d_in[2];
    const float* bih  = (const float*)d_in[3];
    const float* whh  = (const float*)d_in[4];
    const float* bhh  = (const float*)d_in[5];
    const float* wlin = (const float*)d_in[6];
    const float* blin = (const float*)d_in[7];

    float* out = (float*)d_out;
    float* probs_out = out;
    float* hn_out    = out + (size_t)B_DIM * K_DIM;

    const int dyn = NST * STAGE_FLOATS * sizeof(float);   // 184320 B
    cudaFuncSetAttribute(gemm_splitk_kernel<1>, cudaFuncAttributeMaxDynamicSharedMemorySize, dyn);
    cudaFuncSetAttribute(gemm_splitk_kernel<2>, cudaFuncAttributeMaxDynamicSharedMemorySize, dyn);

    // round x,h0 to tf32 once (2*4MB)
    prep_kernel<<<(2 * B_DIM * K_DIM) / (256 * 4), 256>>>(x, h0);

    // GEMM1: partials of x@wih^T + h0@whh^T (fused K=8192, split 4)
    dim3 grid1(K_DIM / BN, 1, SPLITK1);    // (64,1,4) = 256 CTAs
    gemm_splitk_kernel<1><<<grid1, NTHREADS, dyn>>>(wih, whh, (K_DIM / 2) / BK);  // KT=64

    reduce1_kernel<<<(B_DIM * K_DIM) / (256 * 4), 256>>>(bih, bhh, hn_out);

    // GEMM2: partials of hn@wlin^T (K=4096, split 4)
    dim3 grid2(K_DIM / BN, 1, SPLITK2);
    gemm_splitk_kernel<2><<<grid2, NTHREADS, dyn>>>(wlin, nullptr, (K_DIM / SPLITK2) / BK);  // KT=32

    softmax_kernel<<<B_DIM, 256>>>(blin, probs_out);
}

// round 7
// speedup vs baseline: 1.6130x; 1.0759x over previous
#include <cuda_runtime.h>
#include <stdint.h>
#include <math.h>

#define B_DIM 256
#define K_DIM 4096

#define BM 256              // full batch: weights stream once
#define BN 64
#define BK 32
#define ROWF 36             // BK + 4 pad (conflict-free)
#define NST 2
#define STAGE_FLOATS ((BM + BN) * ROWF)            // 11520 floats = 46080 B
#define NTHREADS 256
#define SPLITK1 4           // fused K=8192 -> 2048 per CTA
#define SPLITK2 4           // K=4096 -> 1024 per CTA

// scratch (allocation-free rule)
__device__ float g_part[4 * B_DIM * K_DIM];   // split-K partials (16 MB)
__device__ float g_xh[2 * B_DIM * K_DIM];     // tf32-pre-rounded [x ; h0]
__device__ float g_hn[B_DIM * K_DIM];         // tf32-pre-rounded hidden state

// ---------------- helpers ----------------

__device__ __forceinline__ unsigned f2tf(float f) {
    unsigned r;
    asm("cvt.rna.tf32.f32 %0, %1;" : "=r"(r) : "f"(f));
    return r;
}

__device__ __forceinline__ void mma8(float c[4], const unsigned a[4], const unsigned b[2]) {
    asm volatile(
        "mma.sync.aligned.m16n8k8.row.col.f32.tf32.tf32.f32 "
        "{%0,%1,%2,%3}, {%4,%5,%6,%7}, {%8,%9}, {%0,%1,%2,%3};\n"
        : "+f"(c[0]), "+f"(c[1]), "+f"(c[2]), "+f"(c[3])
        : "r"(a[0]), "r"(a[1]), "r"(a[2]), "r"(a[3]),
          "r"(b[0]), "r"(b[1]));
}

__device__ __forceinline__ void cp_async16(void* smem_dst, const void* gsrc) {
    unsigned s = (unsigned)__cvta_generic_to_shared(smem_dst);
    asm volatile("cp.async.cg.shared.global [%0], [%1], 16;\n" :: "r"(s), "l"(gsrc));
}
__device__ __forceinline__ void cp_commit() {
    asm volatile("cp.async.commit_group;\n");
}
template <int N>
__device__ __forceinline__ void cp_wait() {
    asm volatile("cp.async.wait_group %0;\n" :: "n"(N));
}

// ---------------- prep: round x,h0 to tf32 once ----------------

__global__ void __launch_bounds__(256)
prep_kernel(const float* __restrict__ x, const float* __restrict__ h0) {
    size_t v4 = (size_t)blockIdx.x * 256 + threadIdx.x;
    size_t e = v4 * 4;
    const size_t half = (size_t)B_DIM * K_DIM;
    const float* src = (e < half) ? (x + e) : (h0 + (e - half));
    float4 p = *(const float4*)src;
    *(float4*)(g_xh + e) = make_float4(
        __uint_as_float(f2tf(p.x)), __uint_as_float(f2tf(p.y)),
        __uint_as_float(f2tf(p.z)), __uint_as_float(f2tf(p.w)));
}

// ---------------- GEMM (split-K partial) ----------------
// C tile [256 x 64] over a K range -> g_part[z].
// A: pre-rounded tf32 bits (no cvt). B: raw fp32 weights, cvt in regs.
// Double-buffered SMEM, 2 CTAs/SM for latency hiding.

template <int GEMM>
__global__ void __launch_bounds__(NTHREADS, 2)
gemm_splitk_kernel(const float* __restrict__ w0, const float* __restrict__ w1,
                   int KT) {
    extern __shared__ float sm[];

    const int t = threadIdx.x;
    const int z = blockIdx.z;
    const int bx = blockIdx.x;

    // resolve split-K sources
    const float* A;   // pre-rounded, rows = batch, K-contiguous
    const float* Bw;  // weights, rows = out-features, K-contiguous
    size_t koff;
    if (GEMM == 1) {
        A = g_xh + (z >= 2 ? (size_t)B_DIM * K_DIM : 0);
        Bw = (z < 2) ? w0 : w1;
        koff = (size_t)(z & 1) * (K_DIM / 2);            // 2048
    } else {
        A = g_hn; Bw = w0;
        koff = (size_t)z * (K_DIM / SPLITK2);            // 1024
    }

    // load geometry: 10 vec16 per thread; rows advance by 32 per vec
    const int r0 = t >> 3;          // 0..31
    const int vc = t & 7;           // 16B vec in 128B row
    const float* srcA = A + (size_t)r0 * K_DIM + koff + vc * 4;
    const float* srcB = Bw + ((size_t)(bx * BN + r0)) * K_DIM + koff + vc * 4;
    float* dst0 = sm + r0 * ROWF + vc * 4;

    float acc[4][4][4];
#pragma unroll
    for (int i = 0; i < 4; i++)
#pragma unroll
        for (int j = 0; j < 4; j++)
#pragma unroll
            for (int k = 0; k < 4; k++) acc[i][j][k] = 0.0f;

    const int lane = t & 31, warp = t >> 5;
    const int wm = (warp >> 1) * 64;    // 4 warps along M
    const int wn = (warp & 1) * 32;     // 2 warps along N
    const int g = lane >> 2, tc = lane & 3;

    // prologue: stage 0
    {
#pragma unroll
        for (int i = 0; i < 8; i++) cp_async16(dst0 + i * 32 * ROWF, srcA + (size_t)i * 32 * K_DIM);
#pragma unroll
        for (int i = 0; i < 2; i++) cp_async16(dst0 + (256 + i * 32) * ROWF, srcB + (size_t)i * 32 * K_DIM);
        cp_commit();
    }

#pragma unroll 1
    for (int kt = 0; kt < KT; kt++) {
        // issue next stage (buffer free: bottom barrier of previous iteration)
        if (kt + 1 < KT) {
            float* lb = dst0 + ((kt + 1) & 1) * STAGE_FLOATS;
            size_t ko = (size_t)(kt + 1) * BK;
#pragma unroll
            for (int i = 0; i < 8; i++) cp_async16(lb + i * 32 * ROWF, srcA + ko + (size_t)i * 32 * K_DIM);
#pragma unroll
            for (int i = 0; i < 2; i++) cp_async16(lb + (256 + i * 32) * ROWF, srcB + ko + (size_t)i * 32 * K_DIM);
            cp_commit();
            cp_wait<1>();       // stage kt arrived; stage kt+1 in flight
        } else {
            cp_wait<0>();       // final stage arrived
        }
        __syncthreads();        // all threads' deposits for stage kt visible

        const unsigned* Au = (const unsigned*)(sm + (kt & 1) * STAGE_FLOATS);
        const float*    Bf = (const float*)(Au + 256 * ROWF);
#pragma unroll
        for (int ks = 0; ks < 4; ks++) {
            const int col = ks * 8 + tc;
            unsigned af[4][4];
#pragma unroll
            for (int mi = 0; mi < 4; mi++) {
                int r = wm + mi * 16 + g;
                af[mi][0] = Au[r * ROWF + col];
                af[mi][1] = Au[(r + 8) * ROWF + col];
                af[mi][2] = Au[r * ROWF + col + 4];
                af[mi][3] = Au[(r + 8) * ROWF + col + 4];
            }
            unsigned bf[4][2];
#pragma unroll
            for (int ni = 0; ni < 4; ni++) {
                int r = wn + ni * 8 + g;
                bf[ni][0] = f2tf(Bf[r * ROWF + col]);
                bf[ni][1] = f2tf(Bf[r * ROWF + col + 4]);
            }
#pragma unroll
            for (int mi = 0; mi < 4; mi++)
#pragma unroll
                for (int ni = 0; ni < 4; ni++)
                    mma8(acc[mi][ni], af[mi], bf[ni]);
        }
        __syncthreads();        // stage kt free for reuse at kt+2
    }

    // write partial tile
    float* part = g_part + (size_t)z * (B_DIM * K_DIM);
#pragma unroll
    for (int mi = 0; mi < 4; mi++) {
#pragma unroll
        for (int ni = 0; ni < 4; ni++) {
            int gr = wm + mi * 16 + g;
            int gc = bx * BN + wn + ni * 8 + tc * 2;
            size_t o0 = (size_t)gr * K_DIM + gc;
            size_t o2 = (size_t)(gr + 8) * K_DIM + gc;
            *(float2*)(part + o0) = make_float2(acc[mi][ni][0], acc[mi][ni][1]);
            *(float2*)(part + o2) = make_float2(acc[mi][ni][2], acc[mi][ni][3]);
        }
    }
}

// ---------------- reduce1: hn = tanh(sum partials + bih + bhh) ----------------

__global__ void __launch_bounds__(256)
reduce1_kernel(const float* __restrict__ bih, const float* __restrict__ bhh,
               float* __restrict__ hn_out) {
    size_t v4 = (size_t)blockIdx.x * 256 + threadIdx.x;
    size_t e = v4 * 4;
    int col = (int)(e & (K_DIM - 1));
    float4 p0 = *(const float4*)(g_part + e);
    float4 p1 = *(const float4*)(g_part + (size_t)1 * B_DIM * K_DIM + e);
    float4 p2 = *(const float4*)(g_part + (size_t)2 * B_DIM * K_DIM + e);
    float4 p3 = *(const float4*)(g_part + (size_t)3 * B_DIM * K_DIM + e);
    float4 ba = *(const float4*)(bih + col);
    float4 bb = *(const float4*)(bhh + col);
    float t0 = tanhf(p0.x + p1.x + p2.x + p3.x + ba.x + bb.x);
    float t1 = tanhf(p0.y + p1.y + p2.y + p3.y + ba.y + bb.y);
    float t2 = tanhf(p0.z + p1.z + p2.z + p3.z + ba.z + bb.z);
    float t3 = tanhf(p0.w + p1.w + p2.w + p3.w + ba.w + bb.w);
    *(float4*)(hn_out + e) = make_float4(t0, t1, t2, t3);
    *(float4*)(g_hn + e) = make_float4(__uint_as_float(f2tf(t0)), __uint_as_float(f2tf(t1)),
                                       __uint_as_float(f2tf(t2)), __uint_as_float(f2tf(t3)));
}

// ---------------- softmax (fuses GEMM2 split-K reduce + bias) ----------------

__global__ void __launch_bounds__(256)
softmax_kernel(const float* __restrict__ blin, float* __restrict__ probs) {
    __shared__ float sl[K_DIM];
    __shared__ float red[256];
    const int row = blockIdx.x, tid = threadIdx.x;
    const size_t rb = (size_t)row * K_DIM;

    float m = -1e30f;
    for (int i = tid * 4; i < K_DIM; i += 256 * 4) {
        float4 p0 = *(const float4*)(g_part + rb + i);
        float4 p1 = *(const float4*)(g_part + (size_t)1 * B_DIM * K_DIM + rb + i);
        float4 p2 = *(const float4*)(g_part + (size_t)2 * B_DIM * K_DIM + rb + i);
        float4 p3 = *(const float4*)(g_part + (size_t)3 * B_DIM * K_DIM + rb + i);
        float4 b  = *(const float4*)(blin + i);
        float v0 = p0.x + p1.x + p2.x + p3.x + b.x;
        float v1 = p0.y + p1.y + p2.y + p3.y + b.y;
        float v2 = p0.z + p1.z + p2.z + p3.z + b.z;
        float v3 = p0.w + p1.w + p2.w + p3.w + b.w;
        *(float4*)(sl + i) = make_float4(v0, v1, v2, v3);
        m = fmaxf(m, fmaxf(fmaxf(v0, v1), fmaxf(v2, v3)));
    }
    red[tid] = m;
    __syncthreads();
    for (int s = 128; s > 0; s >>= 1) {
        if (tid < s) red[tid] = fmaxf(red[tid], red[tid + s]);
        __syncthreads();
    }
    m = red[0];
    __syncthreads();

    float sum = 0.0f;
    for (int i = tid; i < K_DIM; i += 256) sum += expf(sl[i] - m);
    red[tid] = sum;
    __syncthreads();
    for (int s = 128; s > 0; s >>= 1) {
        if (tid < s) red[tid] += red[tid + s];
        __syncthreads();
    }
    float inv = 1.0f / red[0];

    for (int i = tid; i < K_DIM; i += 256)
        probs[rb + i] = expf(sl[i] - m) * inv;
}

// ---------------- launch ----------------

extern "C" void kernel_launch(void* const* d_in, const int* in_sizes, int n_in,
                              void* d_out, int out_size) {
    const float* x    = (const float*)d_in[0];
    const float* h0   = (const float*)d_in[1];
    const float* wih  = (const float*)d_in[2];
    const float* bih  = (const float*)d_in[3];
    const float* whh  = (const float*)d_in[4];
    const float* bhh  = (const float*)d_in[5];
    const float* wlin = (const float*)d_in[6];
    const float* blin = (const float*)d_in[7];

    float* out = (float*)d_out;
    float* probs_out = out;
    float* hn_out    = out + (size_t)B_DIM * K_DIM;

    const int dyn = NST * STAGE_FLOATS * sizeof(float);   // 92160 B
    cudaFuncSetAttribute(gemm_splitk_kernel<1>, cudaFuncAttributeMaxDynamicSharedMemorySize, dyn);
    cudaFuncSetAttribute(gemm_splitk_kernel<2>, cudaFuncAttributeMaxDynamicSharedMemorySize, dyn);

    // round x,h0 to tf32 once (2*4MB)
    prep_kernel<<<(2 * B_DIM * K_DIM) / (256 * 4), 256>>>(x, h0);

    // GEMM1: partials of x@wih^T + h0@whh^T (fused K=8192, split 4)
    dim3 grid1(K_DIM / BN, 1, SPLITK1);    // (64,1,4) = 256 CTAs, 2/SM -> 1 wave
    gemm_splitk_kernel<1><<<grid1, NTHREADS, dyn>>>(wih, whh, (K_DIM / 2) / BK);  // KT=64

    reduce1_kernel<<<(B_DIM * K_DIM) / (256 * 4), 256>>>(bih, bhh, hn_out);

    // GEMM2: partials of hn@wlin^T (K=4096, split 4)
    dim3 grid2(K_DIM / BN, 1, SPLITK2);
    gemm_splitk_kernel<2><<<grid2, NTHREADS, dyn>>>(wlin, nullptr, (K_DIM / SPLITK2) / BK);  // KT=32

    softmax_kernel<<<B_DIM, 256>>>(blin, probs_out);
}

// round 8
// speedup vs baseline: 2.4067x; 1.4921x over previous
#include <cuda_runtime.h>
#include <cuda_fp16.h>
#include <stdint.h>
#include <math.h>

#define B_DIM 256
#define K_DIM 4096

#define BM 256              // full batch: weights stream once
#define BN 64
#define BK 32               // K elements per stage
#define PHW 20              // A row pitch in 32-bit words (40 halves, 80B) — conflict-free
#define PBF 40              // B row pitch in floats (160B) — conflict-free LDS.64
#define A_STAGE_WORDS (BM * PHW)              // 5120 (20480 B)
#define B_STAGE_FLOATS (BN * PBF)             // 2560 (10240 B)
#define STAGE_WORDS (A_STAGE_WORDS + B_STAGE_FLOATS)  // 7680 words (30720 B)
#define NST 3
#define NTHREADS 256
#define SPLITK1 4
#define SPLITK2 4

// scratch (allocation-free rule)
__device__ float  g_part[4 * B_DIM * K_DIM];   // split-K partials (16 MB)
__device__ __half g_xh_h[2 * B_DIM * K_DIM];   // fp16 [x ; h0]
__device__ __half g_hn_h[B_DIM * K_DIM];       // fp16 hidden state

// ---------------- helpers ----------------

__device__ __forceinline__ uint32_t pack_f16x2(float lo, float hi) {
    uint32_t d;
    asm("cvt.rn.f16x2.f32 %0, %1, %2;" : "=r"(d) : "f"(hi), "f"(lo));
    return d;
}

__device__ __forceinline__ void mma16(float c[4], const uint32_t a[4], const uint32_t b[2]) {
    asm volatile(
        "mma.sync.aligned.m16n8k16.row.col.f32.f16.f16.f32 "
        "{%0,%1,%2,%3}, {%4,%5,%6,%7}, {%8,%9}, {%0,%1,%2,%3};\n"
        : "+f"(c[0]), "+f"(c[1]), "+f"(c[2]), "+f"(c[3])
        : "r"(a[0]), "r"(a[1]), "r"(a[2]), "r"(a[3]),
          "r"(b[0]), "r"(b[1]));
}

__device__ __forceinline__ void cp_async16(void* smem_dst, const void* gsrc) {
    unsigned s = (unsigned)__cvta_generic_to_shared(smem_dst);
    asm volatile("cp.async.cg.shared.global [%0], [%1], 16;\n" :: "r"(s), "l"(gsrc));
}
__device__ __forceinline__ void cp_commit() {
    asm volatile("cp.async.commit_group;\n");
}
template <int N>
__device__ __forceinline__ void cp_wait() {
    asm volatile("cp.async.wait_group %0;\n" :: "n"(N));
}

// ---------------- prep: convert x,h0 to fp16 once ----------------

__global__ void __launch_bounds__(256)
prep_kernel(const float* __restrict__ x, const float* __restrict__ h0) {
    size_t e = ((size_t)blockIdx.x * 256 + threadIdx.x) * 4;
    const size_t half_n = (size_t)B_DIM * K_DIM;
    const float* src = (e < half_n) ? (x + e) : (h0 + (e - half_n));
    float4 p = *(const float4*)src;
    uint2 o;
    o.x = pack_f16x2(p.x, p.y);
    o.y = pack_f16x2(p.z, p.w);
    *(uint2*)(g_xh_h + e) = o;
}

// ---------------- GEMM (split-K partial, fp16 HMMA) ----------------
// C tile [256 x 64] over a K range -> g_part[z].
// A: fp16 in GMEM/SMEM (no cvt). B: fp32 weights, cvt to f16x2 in regs.

template <int GEMM>
__global__ void __launch_bounds__(NTHREADS, 2)
gemm_splitk_kernel(const float* __restrict__ w0, const float* __restrict__ w1,
                   int KT) {
    extern __shared__ uint32_t smw[];   // NST stages: [A 5120 w][B 2560 w]

    const int t = threadIdx.x;
    const int z = blockIdx.z;
    const int bx = blockIdx.x;

    // resolve split-K sources
    const __half* Ah;
    const float* Bw;
    size_t koff;
    if (GEMM == 1) {
        Ah = g_xh_h + (z >= 2 ? (size_t)B_DIM * K_DIM : 0);
        Bw = (z < 2) ? w0 : w1;
        koff = (size_t)(z & 1) * (K_DIM / 2);            // 2048
    } else {
        Ah = g_hn_h; Bw = w0;
        koff = (size_t)z * (K_DIM / SPLITK2);            // 1024
    }

    // load geometry
    // A: 1024 vec16 per stage (256 rows x 4), 4 per thread
    const int arow = t >> 2, avc = t & 3;
    const __half* srcA = Ah + (size_t)arow * K_DIM + koff + avc * 8;
    uint32_t* dstA = smw + arow * PHW + avc * 4;
    // B: 512 vec16 per stage (64 rows x 8), 2 per thread
    const int brow0 = t >> 3, bvc = t & 7;
    const float* srcB = Bw + ((size_t)(bx * BN + brow0)) * K_DIM + koff + bvc * 4;
    uint32_t* dstB = smw + A_STAGE_WORDS + brow0 * PBF + bvc * 4;

    float acc[4][4][4];
#pragma unroll
    for (int i = 0; i < 4; i++)
#pragma unroll
        for (int j = 0; j < 4; j++)
#pragma unroll
            for (int k = 0; k < 4; k++) acc[i][j][k] = 0.0f;

    const int lane = t & 31, warp = t >> 5;
    const int wm = (warp >> 1) * 64;    // 4 warps along M
    const int wn = (warp & 1) * 32;     // 2 warps along N
    const int g = lane >> 2, tc = lane & 3;

    // prologue: stages 0,1
#pragma unroll
    for (int s = 0; s < NST - 1; s++) {
        uint32_t* da = dstA + s * STAGE_WORDS;
        uint32_t* db = dstB + s * STAGE_WORDS;
        size_t ko = (size_t)s * BK;
#pragma unroll
        for (int i = 0; i < 4; i++) cp_async16(da + i * 64 * PHW, srcA + ko + (size_t)i * 64 * K_DIM);
#pragma unroll
        for (int i = 0; i < 2; i++) cp_async16(db + i * 32 * PBF, srcB + ko + (size_t)i * 32 * K_DIM);
        cp_commit();
    }

#pragma unroll 1
    for (int kt = 0; kt < KT; kt++) {
        if (kt + 2 < KT) {
            const int sl = (kt + 2) % NST;
            uint32_t* da = dstA + sl * STAGE_WORDS;
            uint32_t* db = dstB + sl * STAGE_WORDS;
            size_t ko = (size_t)(kt + 2) * BK;
#pragma unroll
            for (int i = 0; i < 4; i++) cp_async16(da + i * 64 * PHW, srcA + ko + (size_t)i * 64 * K_DIM);
#pragma unroll
            for (int i = 0; i < 2; i++) cp_async16(db + i * 32 * PBF, srcB + ko + (size_t)i * 32 * K_DIM);
            cp_commit();
            cp_wait<2>();
        } else if (kt + 1 < KT) {
            cp_wait<1>();
        } else {
            cp_wait<0>();
        }
        __syncthreads();   // all threads' deposits for stage kt visible

        const uint32_t* Aw = smw + (kt % NST) * STAGE_WORDS;
        const float*    Bf = (const float*)(Aw + A_STAGE_WORDS);
#pragma unroll
        for (int ks2 = 0; ks2 < 2; ks2++) {    // two k16 steps per BK=32
            uint32_t a[4][4];
#pragma unroll
            for (int mi = 0; mi < 4; mi++) {
                int r = wm + mi * 16 + g;
                int base = ks2 * 8 + tc;
                a[mi][0] = Aw[r * PHW + base];
                a[mi][1] = Aw[(r + 8) * PHW + base];
                a[mi][2] = Aw[r * PHW + base + 4];
                a[mi][3] = Aw[(r + 8) * PHW + base + 4];
            }
            uint32_t b[4][2];
#pragma unroll
            for (int ni = 0; ni < 4; ni++) {
                int r = wn + ni * 8 + g;
                const float* bp = Bf + r * PBF + ks2 * 16 + 2 * tc;
                float2 p0 = *(const float2*)bp;
                float2 p1 = *(const float2*)(bp + 8);
                b[ni][0] = pack_f16x2(p0.x, p0.y);
                b[ni][1] = pack_f16x2(p1.x, p1.y);
            }
#pragma unroll
            for (int mi = 0; mi < 4; mi++)
#pragma unroll
                for (int ni = 0; ni < 4; ni++)
                    mma16(acc[mi][ni], a[mi], b[ni]);
        }
        __syncthreads();   // stage kt free for reuse
    }

    // write partial tile
    float* part = g_part + (size_t)z * (B_DIM * K_DIM);
#pragma unroll
    for (int mi = 0; mi < 4; mi++) {
#pragma unroll
        for (int ni = 0; ni < 4; ni++) {
            int gr = wm + mi * 16 + g;
            int gc = bx * BN + wn + ni * 8 + tc * 2;
            size_t o0 = (size_t)gr * K_DIM + gc;
            size_t o2 = (size_t)(gr + 8) * K_DIM + gc;
            *(float2*)(part + o0) = make_float2(acc[mi][ni][0], acc[mi][ni][1]);
            *(float2*)(part + o2) = make_float2(acc[mi][ni][2], acc[mi][ni][3]);
        }
    }
}

// ---------------- reduce1: hn = tanh(sum partials + bih + bhh) ----------------

__global__ void __launch_bounds__(256)
reduce1_kernel(const float* __restrict__ bih, const float* __restrict__ bhh,
               float* __restrict__ hn_out) {
    size_t e = ((size_t)blockIdx.x * 256 + threadIdx.x) * 4;
    int col = (int)(e & (K_DIM - 1));
    float4 p0 = *(const float4*)(g_part + e);
    float4 p1 = *(const float4*)(g_part + (size_t)1 * B_DIM * K_DIM + e);
    float4 p2 = *(const float4*)(g_part + (size_t)2 * B_DIM * K_DIM + e);
    float4 p3 = *(const float4*)(g_part + (size_t)3 * B_DIM * K_DIM + e);
    float4 ba = *(const float4*)(bih + col);
    float4 bb = *(const float4*)(bhh + col);
    float t0 = tanhf(p0.x + p1.x + p2.x + p3.x + ba.x + bb.x);
    float t1 = tanhf(p0.y + p1.y + p2.y + p3.y + ba.y + bb.y);
    float t2 = tanhf(p0.z + p1.z + p2.z + p3.z + ba.z + bb.z);
    float t3 = tanhf(p0.w + p1.w + p2.w + p3.w + ba.w + bb.w);
    *(float4*)(hn_out + e) = make_float4(t0, t1, t2, t3);
    uint2 o;
    o.x = pack_f16x2(t0, t1);
    o.y = pack_f16x2(t2, t3);
    *(uint2*)(g_hn_h + e) = o;
}

// ---------------- softmax (fuses GEMM2 split-K reduce + bias) ----------------

__global__ void __launch_bounds__(256)
softmax_kernel(const float* __restrict__ blin, float* __restrict__ probs) {
    __shared__ float sl[K_DIM];
    __shared__ float red[256];
    const int row = blockIdx.x, tid = threadIdx.x;
    const size_t rb = (size_t)row * K_DIM;

    float m = -1e30f;
    for (int i = tid * 4; i < K_DIM; i += 256 * 4) {
        float4 p0 = *(const float4*)(g_part + rb + i);
        float4 p1 = *(const float4*)(g_part + (size_t)1 * B_DIM * K_DIM + rb + i);
        float4 p2 = *(const float4*)(g_part + (size_t)2 * B_DIM * K_DIM + rb + i);
        float4 p3 = *(const float4*)(g_part + (size_t)3 * B_DIM * K_DIM + rb + i);
        float4 b  = *(const float4*)(blin + i);
        float v0 = p0.x + p1.x + p2.x + p3.x + b.x;
        float v1 = p0.y + p1.y + p2.y + p3.y + b.y;
        float v2 = p0.z + p1.z + p2.z + p3.z + b.z;
        float v3 = p0.w + p1.w + p2.w + p3.w + b.w;
        *(float4*)(sl + i) = make_float4(v0, v1, v2, v3);
        m = fmaxf(m, fmaxf(fmaxf(v0, v1), fmaxf(v2, v3)));
    }
    red[tid] = m;
    __syncthreads();
    for (int s = 128; s > 0; s >>= 1) {
        if (tid < s) red[tid] = fmaxf(red[tid], red[tid + s]);
        __syncthreads();
    }
    m = red[0];
    __syncthreads();

    float sum = 0.0f;
    for (int i = tid; i < K_DIM; i += 256) sum += expf(sl[i] - m);
    red[tid] = sum;
    __syncthreads();
    for (int s = 128; s > 0; s >>= 1) {
        if (tid < s) red[tid] += red[tid + s];
        __syncthreads();
    }
    float inv = 1.0f / red[0];

    for (int i = tid; i < K_DIM; i += 256)
        probs[rb + i] = expf(sl[i] - m) * inv;
}

// ---------------- launch ----------------

extern "C" void kernel_launch(void* const* d_in, const int* in_sizes, int n_in,
                              void* d_out, int out_size) {
    const float* x    = (const float*)d_in[0];
    const float* h0   = (const float*)d_in[1];
    const float* wih  = (const float*)d_in[2];
    const float* bih  = (const float*)d_in[3];
    const float* whh  = (const float*)d_in[4];
    const float* bhh  = (const float*)d_in[5];
    const float* wlin = (const float*)d_in[6];
    const float* blin = (const float*)d_in[7];

    float* out = (float*)d_out;
    float* probs_out = out;
    float* hn_out    = out + (size_t)B_DIM * K_DIM;

    const int dyn = NST * STAGE_WORDS * sizeof(uint32_t);   // 92160 B
    cudaFuncSetAttribute(gemm_splitk_kernel<1>, cudaFuncAttributeMaxDynamicSharedMemorySize, dyn);
    cudaFuncSetAttribute(gemm_splitk_kernel<2>, cudaFuncAttributeMaxDynamicSharedMemorySize, dyn);

    // convert x,h0 to fp16 once
    prep_kernel<<<(2 * B_DIM * K_DIM) / (256 * 4), 256>>>(x, h0);

    // GEMM1: partials of x@wih^T + h0@whh^T (fused K=8192, split 4)
    dim3 grid1(K_DIM / BN, 1, SPLITK1);    // (64,1,4) = 256 CTAs
    gemm_splitk_kernel<1><<<grid1, NTHREADS, dyn>>>(wih, whh, (K_DIM / 2) / BK);  // KT=64

    reduce1_kernel<<<(B_DIM * K_DIM) / (256 * 4), 256>>>(bih, bhh, hn_out);

    // GEMM2: partials of hn@wlin^T (K=4096, split 4)
    dim3 grid2(K_DIM / BN, 1, SPLITK2);
    gemm_splitk_kernel<2><<<grid2, NTHREADS, dyn>>>(wlin, nullptr, (K_DIM / SPLITK2) / BK);  // KT=32

    softmax_kernel<<<B_DIM, 256>>>(blin, probs_out);
}

// round 9
// speedup vs baseline: 2.8364x; 1.1786x over previous
#include <cuda_runtime.h>
#include <cuda_fp16.h>
#include <stdint.h>
#include <math.h>

#define B_DIM 256
#define K_DIM 4096

#define BM 256              // full batch: weights stream once
#define BN 64
#define BK 64               // K elements per stage
#define PHW 36              // A row pitch in words (64 halves + pad; bank = 4g+tc distinct)
#define PBF 72              // B row pitch in floats (64 floats + pad; same class as R8's 40)
#define A_STAGE_WORDS (BM * PHW)                      // 9216 w (36864 B)
#define B_STAGE_WORDS (BN * PBF)                      // 4608 w (18432 B)
#define STAGE_WORDS (A_STAGE_WORDS + B_STAGE_WORDS)   // 13824 w (55296 B)
#define NST 2
#define NTHREADS 256
#define SPLITK1 4
#define SPLITK2 4

// scratch (allocation-free rule)
__device__ float  g_part[4 * B_DIM * K_DIM];   // split-K partials (16 MB)
__device__ __half g_xh_h[2 * B_DIM * K_DIM];   // fp16 [x ; h0]
__device__ __half g_hn_h[B_DIM * K_DIM];       // fp16 hidden state

// ---------------- helpers ----------------

__device__ __forceinline__ uint32_t pack_f16x2(float lo, float hi) {
    uint32_t d;
    asm("cvt.rn.f16x2.f32 %0, %1, %2;" : "=r"(d) : "f"(hi), "f"(lo));
    return d;
}

__device__ __forceinline__ void mma16(float c[4], const uint32_t a[4], const uint32_t b[2]) {
    asm volatile(
        "mma.sync.aligned.m16n8k16.row.col.f32.f16.f16.f32 "
        "{%0,%1,%2,%3}, {%4,%5,%6,%7}, {%8,%9}, {%0,%1,%2,%3};\n"
        : "+f"(c[0]), "+f"(c[1]), "+f"(c[2]), "+f"(c[3])
        : "r"(a[0]), "r"(a[1]), "r"(a[2]), "r"(a[3]),
          "r"(b[0]), "r"(b[1]));
}

__device__ __forceinline__ void cp_async16(void* smem_dst, const void* gsrc) {
    unsigned s = (unsigned)__cvta_generic_to_shared(smem_dst);
    asm volatile("cp.async.cg.shared.global [%0], [%1], 16;\n" :: "r"(s), "l"(gsrc));
}
__device__ __forceinline__ void cp_commit() {
    asm volatile("cp.async.commit_group;\n");
}
template <int N>
__device__ __forceinline__ void cp_wait() {
    asm volatile("cp.async.wait_group %0;\n" :: "n"(N));
}

// ---------------- prep: convert x,h0 to fp16 once ----------------

__global__ void __launch_bounds__(256)
prep_kernel(const float* __restrict__ x, const float* __restrict__ h0) {
    size_t e = ((size_t)blockIdx.x * 256 + threadIdx.x) * 4;
    const size_t half_n = (size_t)B_DIM * K_DIM;
    const float* src = (e < half_n) ? (x + e) : (h0 + (e - half_n));
    float4 p = *(const float4*)src;
    uint2 o;
    o.x = pack_f16x2(p.x, p.y);
    o.y = pack_f16x2(p.z, p.w);
    *(uint2*)(g_xh_h + e) = o;
}

// ---------------- GEMM (split-K partial, fp16 HMMA, BK=64 double-buffer) ----------------

template <int GEMM>
__global__ void __launch_bounds__(NTHREADS, 2)
gemm_splitk_kernel(const float* __restrict__ w0, const float* __restrict__ w1,
                   int KT) {
    extern __shared__ uint32_t smw[];   // 2 stages: [A 9216 w][B 4608 w]

    const int t = threadIdx.x;
    const int z = blockIdx.z;
    const int bx = blockIdx.x;

    // resolve split-K sources
    const __half* Ah;
    const float* Bw;
    size_t koff;
    if (GEMM == 1) {
        Ah = g_xh_h + (z >= 2 ? (size_t)B_DIM * K_DIM : 0);
        Bw = (z < 2) ? w0 : w1;
        koff = (size_t)(z & 1) * (K_DIM / 2);            // 2048
    } else {
        Ah = g_hn_h; Bw = w0;
        koff = (size_t)z * (K_DIM / SPLITK2);            // 1024
    }

    // load geometry
    // A: 2048 vec16 per stage (256 rows x 8), 8 per thread; row = v>>3, vc = v&7
    const int arow = t >> 3, avc = t & 7;                // i-th vec: row arow+32i
    const __half* srcA = Ah + (size_t)arow * K_DIM + koff + avc * 8;
    uint32_t* dstA = smw + arow * PHW + avc * 4;
    // B: 1024 vec16 per stage (64 rows x 16), 4 per thread; row = v>>4, vc = v&15
    const int brow = t >> 4, bvc = t & 15;               // i-th vec: row brow+16i
    const float* srcB = Bw + ((size_t)(bx * BN + brow)) * K_DIM + koff + bvc * 4;
    uint32_t* dstB = smw + A_STAGE_WORDS + brow * PBF + bvc * 4;

    float acc[4][4][4];
#pragma unroll
    for (int i = 0; i < 4; i++)
#pragma unroll
        for (int j = 0; j < 4; j++)
#pragma unroll
            for (int k = 0; k < 4; k++) acc[i][j][k] = 0.0f;

    const int lane = t & 31, warp = t >> 5;
    const int wm = (warp >> 1) * 64;    // 4 warps along M
    const int wn = (warp & 1) * 32;     // 2 warps along N
    const int g = lane >> 2, tc = lane & 3;

    // prologue: stage 0
    {
#pragma unroll
        for (int i = 0; i < 8; i++) cp_async16(dstA + i * 32 * PHW, srcA + (size_t)i * 32 * K_DIM);
#pragma unroll
        for (int i = 0; i < 4; i++) cp_async16(dstB + i * 16 * PBF, srcB + (size_t)i * 16 * K_DIM);
        cp_commit();
    }

#pragma unroll 1
    for (int kt = 0; kt < KT; kt++) {
        if (kt + 1 < KT) {
            const int sl = (kt + 1) & 1;
            uint32_t* da = dstA + sl * STAGE_WORDS;
            uint32_t* db = dstB + sl * STAGE_WORDS;
            size_t ko = (size_t)(kt + 1) * BK;
#pragma unroll
            for (int i = 0; i < 8; i++) cp_async16(da + i * 32 * PHW, srcA + ko + (size_t)i * 32 * K_DIM);
#pragma unroll
            for (int i = 0; i < 4; i++) cp_async16(db + i * 16 * PBF, srcB + ko + (size_t)i * 16 * K_DIM);
            cp_commit();
            cp_wait<1>();
        } else {
            cp_wait<0>();
        }
        __syncthreads();   // all threads' deposits for stage kt visible

        const uint32_t* Aw = smw + (kt & 1) * STAGE_WORDS;
        const float*    Bf = (const float*)(Aw + A_STAGE_WORDS);
#pragma unroll
        for (int ks2 = 0; ks2 < 4; ks2++) {    // four k16 steps per BK=64
            uint32_t a[4][4];
#pragma unroll
            for (int mi = 0; mi < 4; mi++) {
                int r = wm + mi * 16 + g;
                int base = ks2 * 8 + tc;
                a[mi][0] = Aw[r * PHW + base];
                a[mi][1] = Aw[(r + 8) * PHW + base];
                a[mi][2] = Aw[r * PHW + base + 4];
                a[mi][3] = Aw[(r + 8) * PHW + base + 4];
            }
            uint32_t b[4][2];
#pragma unroll
            for (int ni = 0; ni < 4; ni++) {
                int r = wn + ni * 8 + g;
                const float* bp = Bf + r * PBF + ks2 * 16 + 2 * tc;
                float2 p0 = *(const float2*)bp;
                float2 p1 = *(const float2*)(bp + 8);
                b[ni][0] = pack_f16x2(p0.x, p0.y);
                b[ni][1] = pack_f16x2(p1.x, p1.y);
            }
#pragma unroll
            for (int mi = 0; mi < 4; mi++)
#pragma unroll
                for (int ni = 0; ni < 4; ni++)
                    mma16(acc[mi][ni], a[mi], b[ni]);
        }
        __syncthreads();   // stage kt free for reuse
    }

    // write partial tile
    float* part = g_part + (size_t)z * (B_DIM * K_DIM);
#pragma unroll
    for (int mi = 0; mi < 4; mi++) {
#pragma unroll
        for (int ni = 0; ni < 4; ni++) {
            int gr = wm + mi * 16 + g;
            int gc = bx * BN + wn + ni * 8 + tc * 2;
            size_t o0 = (size_t)gr * K_DIM + gc;
            size_t o2 = (size_t)(gr + 8) * K_DIM + gc;
            *(float2*)(part + o0) = make_float2(acc[mi][ni][0], acc[mi][ni][1]);
            *(float2*)(part + o2) = make_float2(acc[mi][ni][2], acc[mi][ni][3]);
        }
    }
}

// ---------------- reduce1: hn = tanh(sum partials + bih + bhh) ----------------

__global__ void __launch_bounds__(256)
reduce1_kernel(const float* __restrict__ bih, const float* __restrict__ bhh,
               float* __restrict__ hn_out) {
    size_t e = ((size_t)blockIdx.x * 256 + threadIdx.x) * 4;
    int col = (int)(e & (K_DIM - 1));
    float4 p0 = *(const float4*)(g_part + e);
    float4 p1 = *(const float4*)(g_part + (size_t)1 * B_DIM * K_DIM + e);
    float4 p2 = *(const float4*)(g_part + (size_t)2 * B_DIM * K_DIM + e);
    float4 p3 = *(const float4*)(g_part + (size_t)3 * B_DIM * K_DIM + e);
    float4 ba = *(const float4*)(bih + col);
    float4 bb = *(const float4*)(bhh + col);
    float t0 = tanhf(p0.x + p1.x + p2.x + p3.x + ba.x + bb.x);
    float t1 = tanhf(p0.y + p1.y + p2.y + p3.y + ba.y + bb.y);
    float t2 = tanhf(p0.z + p1.z + p2.z + p3.z + ba.z + bb.z);
    float t3 = tanhf(p0.w + p1.w + p2.w + p3.w + ba.w + bb.w);
    *(float4*)(hn_out + e) = make_float4(t0, t1, t2, t3);
    uint2 o;
    o.x = pack_f16x2(t0, t1);
    o.y = pack_f16x2(t2, t3);
    *(uint2*)(g_hn_h + e) = o;
}

// ---------------- softmax (fuses GEMM2 split-K reduce + bias) ----------------

__global__ void __launch_bounds__(256)
softmax_kernel(const float* __restrict__ blin, float* __restrict__ probs) {
    __shared__ float sl[K_DIM];
    __shared__ float red[256];
    const int row = blockIdx.x, tid = threadIdx.x;
    const size_t rb = (size_t)row * K_DIM;

    float m = -1e30f;
    for (int i = tid * 4; i < K_DIM; i += 256 * 4) {
        float4 p0 = *(const float4*)(g_part + rb + i);
        float4 p1 = *(const float4*)(g_part + (size_t)1 * B_DIM * K_DIM + rb + i);
        float4 p2 = *(const float4*)(g_part + (size_t)2 * B_DIM * K_DIM + rb + i);
        float4 p3 = *(const float4*)(g_part + (size_t)3 * B_DIM * K_DIM + rb + i);
        float4 b  = *(const float4*)(blin + i);
        float v0 = p0.x + p1.x + p2.x + p3.x + b.x;
        float v1 = p0.y + p1.y + p2.y + p3.y + b.y;
        float v2 = p0.z + p1.z + p2.z + p3.z + b.z;
        float v3 = p0.w + p1.w + p2.w + p3.w + b.w;
        *(float4*)(sl + i) = make_float4(v0, v1, v2, v3);
        m = fmaxf(m, fmaxf(fmaxf(v0, v1), fmaxf(v2, v3)));
    }
    red[tid] = m;
    __syncthreads();
    for (int s = 128; s > 0; s >>= 1) {
        if (tid < s) red[tid] = fmaxf(red[tid], red[tid + s]);
        __syncthreads();
    }
    m = red[0];
    __syncthreads();

    float sum = 0.0f;
    for (int i = tid; i < K_DIM; i += 256) sum += expf(sl[i] - m);
    red[tid] = sum;
    __syncthreads();
    for (int s = 128; s > 0; s >>= 1) {
        if (tid < s) red[tid] += red[tid + s];
        __syncthreads();
    }
    float inv = 1.0f / red[0];

    for (int i = tid; i < K_DIM; i += 256)
        probs[rb + i] = expf(sl[i] - m) * inv;
}

// ---------------- launch ----------------

extern "C" void kernel_launch(void* const* d_in, const int* in_sizes, int n_in,
                              void* d_out, int out_size) {
    const float* x    = (const float*)d_in[0];
    const float* h0   = (const float*)d_in[1];
    const float* wih  = (const float*)d_in[2];
    const float* bih  = (const float*)d_in[3];
    const float* whh  = (const float*)d_in[4];
    const float* bhh  = (const float*)d_in[5];
    const float* wlin = (const float*)d_in[6];
    const float* blin = (const float*)d_in[7];

    float* out = (float*)d_out;
    float* probs_out = out;
    float* hn_out    = out + (size_t)B_DIM * K_DIM;

    const int dyn = NST * STAGE_WORDS * sizeof(uint32_t);   // 110592 B
    cudaFuncSetAttribute(gemm_splitk_kernel<1>, cudaFuncAttributeMaxDynamicSharedMemorySize, dyn);
    cudaFuncSetAttribute(gemm_splitk_kernel<2>, cudaFuncAttributeMaxDynamicSharedMemorySize, dyn);

    // convert x,h0 to fp16 once
    prep_kernel<<<(2 * B_DIM * K_DIM) / (256 * 4), 256>>>(x, h0);

    // GEMM1: partials of x@wih^T + h0@whh^T (fused K=8192, split 4)
    dim3 grid1(K_DIM / BN, 1, SPLITK1);    // (64,1,4) = 256 CTAs
    gemm_splitk_kernel<1><<<grid1, NTHREADS, dyn>>>(wih, whh, (K_DIM / 2) / BK);  // KT=32

    reduce1_kernel<<<(B_DIM * K_DIM) / (256 * 4), 256>>>(bih, bhh, hn_out);

    // GEMM2: partials of hn@wlin^T (K=4096, split 4)
    dim3 grid2(K_DIM / BN, 1, SPLITK2);
    gemm_splitk_kernel<2><<<grid2, NTHREADS, dyn>>>(wlin, nullptr, (K_DIM / SPLITK2) / BK);  // KT=16

    softmax_kernel<<<B_DIM, 256>>>(blin, probs_out);
}

// round 11
// speedup vs baseline: 3.0036x; 1.0589x over previous
#include <cuda_runtime.h>
#include <cuda_fp16.h>
#include <stdint.h>
#include <math.h>

#define B_DIM 256
#define K_DIM 4096

#define BM 256              // full batch per CTA
#define BN 128
#define BK 64               // K elements per stage
#define PHW 36              // A row pitch in words (64 halves + pad) — conflict-free
#define PBF 72              // B row pitch in floats (64 floats + pad) — conflict-free
#define A_STAGE_WORDS (BM * PHW)                      // 9216 w (36864 B)
#define B_STAGE_WORDS (BN * PBF)                      // 9216 w (36864 B)
#define STAGE_WORDS (A_STAGE_WORDS + B_STAGE_WORDS)   // 18432 w (73728 B)
#define NST 2
#define NTHREADS 256
#define SPLITK1 4
#define SPLITK2 4

// scratch (allocation-free rule)
__device__ float  g_part[4 * B_DIM * K_DIM];   // split-K partials (16 MB)
__device__ __half g_xh_h[2 * B_DIM * K_DIM];   // fp16 [x ; h0]
__device__ __half g_hn_h[B_DIM * K_DIM];       // fp16 hidden state

// ---------------- helpers ----------------

__device__ __forceinline__ uint32_t pack_f16x2(float lo, float hi) {
    uint32_t d;
    asm("cvt.rn.f16x2.f32 %0, %1, %2;" : "=r"(d) : "f"(hi), "f"(lo));
    return d;
}

__device__ __forceinline__ void mma16(float c[4], const uint32_t a[4], const uint32_t b[2]) {
    asm volatile(
        "mma.sync.aligned.m16n8k16.row.col.f32.f16.f16.f32 "
        "{%0,%1,%2,%3}, {%4,%5,%6,%7}, {%8,%9}, {%0,%1,%2,%3};\n"
        : "+f"(c[0]), "+f"(c[1]), "+f"(c[2]), "+f"(c[3])
        : "r"(a[0]), "r"(a[1]), "r"(a[2]), "r"(a[3]),
          "r"(b[0]), "r"(b[1]));
}

__device__ __forceinline__ void cp_async16(void* smem_dst, const void* gsrc) {
    unsigned s = (unsigned)__cvta_generic_to_shared(smem_dst);
    asm volatile("cp.async.cg.shared.global [%0], [%1], 16;\n" :: "r"(s), "l"(gsrc));
}
__device__ __forceinline__ void cp_commit() {
    asm volatile("cp.async.commit_group;\n");
}
template <int N>
__device__ __forceinline__ void cp_wait() {
    asm volatile("cp.async.wait_group %0;\n" :: "n"(N));
}

// ---------------- prep: convert x,h0 to fp16 once ----------------

__global__ void __launch_bounds__(256)
prep_kernel(const float* __restrict__ x, const float* __restrict__ h0) {
    size_t e = ((size_t)blockIdx.x * 256 + threadIdx.x) * 4;
    const size_t half_n = (size_t)B_DIM * K_DIM;
    const float* src = (e < half_n) ? (x + e) : (h0 + (e - half_n));
    float4 p = *(const float4*)src;
    uint2 o;
    o.x = pack_f16x2(p.x, p.y);
    o.y = pack_f16x2(p.z, p.w);
    *(uint2*)(g_xh_h + e) = o;
}

// ---------------- GEMM (split-K partial, fp16 HMMA, warp tile 64x64) ----------------

template <int GEMM>
__global__ void __launch_bounds__(NTHREADS, 1)
gemm_splitk_kernel(const float* __restrict__ w0, const float* __restrict__ w1,
                   int KT) {
    extern __shared__ uint32_t smw[];   // 2 stages: [A 9216 w][B 9216 w]

    const int t = threadIdx.x;
    const int z = blockIdx.z;
    const int bx = blockIdx.x;

    // resolve split-K sources
    const __half* Ah;
    const float* Bw;
    size_t koff;
    if (GEMM == 1) {
        Ah = g_xh_h + (z >= 2 ? (size_t)B_DIM * K_DIM : 0);
        Bw = (z < 2) ? w0 : w1;
        koff = (size_t)(z & 1) * (K_DIM / 2);            // 2048
    } else {
        Ah = g_hn_h; Bw = w0;
        koff = (size_t)z * (K_DIM / SPLITK2);            // 1024
    }

    // load geometry
    // A: 2048 vec16/stage (256 rows x 8), 8 per thread; rows step +32
    const int arow = t >> 3, avc = t & 7;
    const __half* srcA = Ah + (size_t)arow * K_DIM + koff + avc * 8;
    uint32_t* dstA = smw + arow * PHW + avc * 4;
    // B: 2048 vec16/stage (128 rows x 16), 8 per thread; rows step +16
    const int brow = t >> 4, bvc = t & 15;
    const float* srcB = Bw + ((size_t)(bx * BN + brow)) * K_DIM + koff + bvc * 4;
    uint32_t* dstB = smw + A_STAGE_WORDS + brow * PBF + bvc * 4;

    float acc[4][8][4];
#pragma unroll
    for (int i = 0; i < 4; i++)
#pragma unroll
        for (int j = 0; j < 8; j++)
#pragma unroll
            for (int k = 0; k < 4; k++) acc[i][j][k] = 0.0f;

    const int lane = t & 31, warp = t >> 5;
    const int wm = (warp >> 1) * 64;    // 4 warps along M
    const int wn = (warp & 1) * 64;     // 2 warps along N (64 cols each)
    const int g = lane >> 2, tc = lane & 3;

    // prologue: stage 0
    {
#pragma unroll
        for (int i = 0; i < 8; i++) cp_async16(dstA + i * 32 * PHW, srcA + (size_t)i * 32 * K_DIM);
#pragma unroll
        for (int i = 0; i < 8; i++) cp_async16(dstB + i * 16 * PBF, srcB + (size_t)i * 16 * K_DIM);
        cp_commit();
    }

#pragma unroll 1
    for (int kt = 0; kt < KT; kt++) {
        if (kt + 1 < KT) {
            const int sl = (kt + 1) & 1;
            uint32_t* da = dstA + sl * STAGE_WORDS;
            uint32_t* db = dstB + sl * STAGE_WORDS;
            size_t ko = (size_t)(kt + 1) * BK;
#pragma unroll
            for (int i = 0; i < 8; i++) cp_async16(da + i * 32 * PHW, srcA + ko + (size_t)i * 32 * K_DIM);
#pragma unroll
            for (int i = 0; i < 8; i++) cp_async16(db + i * 16 * PBF, srcB + ko + (size_t)i * 16 * K_DIM);
            cp_commit();
            cp_wait<1>();
        } else {
            cp_wait<0>();
        }
        __syncthreads();   // all threads' deposits for stage kt visible

        const uint32_t* Aw = smw + (kt & 1) * STAGE_WORDS;
        const float*    Bf = (const float*)(Aw + A_STAGE_WORDS);
#pragma unroll
        for (int ks2 = 0; ks2 < 4; ks2++) {    // four k16 steps per BK=64
            uint32_t a[4][4];
#pragma unroll
            for (int mi = 0; mi < 4; mi++) {
                int r = wm + mi * 16 + g;
                int base = ks2 * 8 + tc;
                a[mi][0] = Aw[r * PHW + base];
                a[mi][1] = Aw[(r + 8) * PHW + base];
                a[mi][2] = Aw[r * PHW + base + 4];
                a[mi][3] = Aw[(r + 8) * PHW + base + 4];
            }
            uint32_t b[8][2];
#pragma unroll
            for (int ni = 0; ni < 8; ni++) {
                int r = wn + ni * 8 + g;
                const float* bp = Bf + r * PBF + ks2 * 16 + 2 * tc;
                float2 p0 = *(const float2*)bp;
                float2 p1 = *(const float2*)(bp + 8);
                b[ni][0] = pack_f16x2(p0.x, p0.y);
                b[ni][1] = pack_f16x2(p1.x, p1.y);
            }
#pragma unroll
            for (int mi = 0; mi < 4; mi++)
#pragma unroll
                for (int ni = 0; ni < 8; ni++)
                    mma16(acc[mi][ni], a[mi], b[ni]);
        }
        __syncthreads();   // stage kt free for reuse
    }

    // write partial tile
    float* part = g_part + (size_t)z * (B_DIM * K_DIM);
#pragma unroll
    for (int mi = 0; mi < 4; mi++) {
#pragma unroll
        for (int ni = 0; ni < 8; ni++) {
            int gr = wm + mi * 16 + g;
            int gc = bx * BN + wn + ni * 8 + tc * 2;
            size_t o0 = (size_t)gr * K_DIM + gc;
            size_t o2 = (size_t)(gr + 8) * K_DIM + gc;
            *(float2*)(part + o0) = make_float2(acc[mi][ni][0], acc[mi][ni][1]);
            *(float2*)(part + o2) = make_float2(acc[mi][ni][2], acc[mi][ni][3]);
        }
    }
}

// ---------------- reduce1: hn = tanh(sum partials + bih + bhh) ----------------

__global__ void __launch_bounds__(256)
reduce1_kernel(const float* __restrict__ bih, const float* __restrict__ bhh,
               float* __restrict__ hn_out) {
    size_t e = ((size_t)blockIdx.x * 256 + threadIdx.x) * 4;
    int col = (int)(e & (K_DIM - 1));
    float4 p0 = *(const float4*)(g_part + e);
    float4 p1 = *(const float4*)(g_part + (size_t)1 * B_DIM * K_DIM + e);
    float4 p2 = *(const float4*)(g_part + (size_t)2 * B_DIM * K_DIM + e);
    float4 p3 = *(const float4*)(g_part + (size_t)3 * B_DIM * K_DIM + e);
    float4 ba = *(const float4*)(bih + col);
    float4 bb = *(const float4*)(bhh + col);
    float t0 = tanhf(p0.x + p1.x + p2.x + p3.x + ba.x + bb.x);
    float t1 = tanhf(p0.y + p1.y + p2.y + p3.y + ba.y + bb.y);
    float t2 = tanhf(p0.z + p1.z + p2.z + p3.z + ba.z + bb.z);
    float t3 = tanhf(p0.w + p1.w + p2.w + p3.w + ba.w + bb.w);
    *(float4*)(hn_out + e) = make_float4(t0, t1, t2, t3);
    uint2 o;
    o.x = pack_f16x2(t0, t1);
    o.y = pack_f16x2(t2, t3);
    *(uint2*)(g_hn_h + e) = o;
}

// ---------------- softmax (fuses GEMM2 split-K reduce + bias) ----------------

#define SMT 512

__global__ void __launch_bounds__(SMT)
softmax_kernel(const float* __restrict__ blin, float* __restrict__ probs) {
    __shared__ float sl[K_DIM];
    __shared__ float red[SMT];
    const int row = blockIdx.x, tid = threadIdx.x;
    const size_t rb = (size_t)row * K_DIM;

    float m = -1e30f;
    for (int i = tid * 4; i < K_DIM; i += SMT * 4) {
        float4 p0 = *(const float4*)(g_part + rb + i);
        float4 p1 = *(const float4*)(g_part + (size_t)1 * B_DIM * K_DIM + rb + i);
        float4 p2 = *(const float4*)(g_part + (size_t)2 * B_DIM * K_DIM + rb + i);
        float4 p3 = *(const float4*)(g_part + (size_t)3 * B_DIM * K_DIM + rb + i);
        float4 b  = *(const float4*)(blin + i);
        float v0 = p0.x + p1.x + p2.x + p3.x + b.x;
        float v1 = p0.y + p1.y + p2.y + p3.y + b.y;
        float v2 = p0.z + p1.z + p2.z + p3.z + b.z;
        float v3 = p0.w + p1.w + p2.w + p3.w + b.w;
        *(float4*)(sl + i) = make_float4(v0, v1, v2, v3);
        m = fmaxf(m, fmaxf(fmaxf(v0, v1), fmaxf(v2, v3)));
    }
    red[tid] = m;
    __syncthreads();
    for (int s = SMT / 2; s > 0; s >>= 1) {
        if (tid < s) red[tid] = fmaxf(red[tid], red[tid + s]);
        __syncthreads();
    }
    m = red[0];
    __syncthreads();

    float sum = 0.0f;
    for (int i = tid; i < K_DIM; i += SMT) sum += expf(sl[i] - m);
    red[tid] = sum;
    __syncthreads();
    for (int s = SMT / 2; s > 0; s >>= 1) {
        if (tid < s) red[tid] += red[tid + s];
        __syncthreads();
    }
    float inv = 1.0f / red[0];

    for (int i = tid; i < K_DIM; i += SMT)
        probs[rb + i] = expf(sl[i] - m) * inv;
}

// ---------------- launch ----------------

extern "C" void kernel_launch(void* const* d_in, const int* in_sizes, int n_in,
                              void* d_out, int out_size) {
    const float* x    = (const float*)d_in[0];
    const float* h0   = (const float*)d_in[1];
    const float* wih  = (const float*)d_in[2];
    const float* bih  = (const float*)d_in[3];
    const float* whh  = (const float*)d_in[4];
    const float* bhh  = (const float*)d_in[5];
    const float* wlin = (const float*)d_in[6];
    const float* blin = (const float*)d_in[7];

    float* out = (float*)d_out;
    float* probs_out = out;
    float* hn_out    = out + (size_t)B_DIM * K_DIM;

    const int dyn = NST * STAGE_WORDS * sizeof(uint32_t);   // 147456 B
    cudaFuncSetAttribute(gemm_splitk_kernel<1>, cudaFuncAttributeMaxDynamicSharedMemorySize, dyn);
    cudaFuncSetAttribute(gemm_splitk_kernel<2>, cudaFuncAttributeMaxDynamicSharedMemorySize, dyn);

    // convert x,h0 to fp16 once
    prep_kernel<<<(2 * B_DIM * K_DIM) / (256 * 4), 256>>>(x, h0);

    // GEMM1: partials of x@wih^T + h0@whh^T (fused K=8192, split 4)
    dim3 grid1(K_DIM / BN, 1, SPLITK1);    // (32,1,4) = 128 CTAs
    gemm_splitk_kernel<1><<<grid1, NTHREADS, dyn>>>(wih, whh, (K_DIM / 2) / BK);  // KT=32

    reduce1_kernel<<<(B_DIM * K_DIM) / (256 * 4), 256>>>(bih, bhh, hn_out);

    // GEMM2: partials of hn@wlin^T (K=4096, split 4)
    dim3 grid2(K_DIM / BN, 1, SPLITK2);
    gemm_splitk_kernel<2><<<grid2, NTHREADS, dyn>>>(wlin, nullptr, (K_DIM / SPLITK2) / BK);  // KT=16

    softmax_kernel<<<B_DIM, SMT>>>(blin, probs_out);
}